// round 2
// baseline (speedup 1.0000x reference)
#include <cuda_runtime.h>
#include <math.h>

// Problem constants
#define Bq   64
#define Tq   128
#define Eq   300
#define Hq   512
#define Cq   256
#define Mq   512
#define RPS  (Bq*Tq)      // rows per sequence: 8192
#define NROWS (2*RPS)     // 16384
#define G4H  (4*Hq)       // 2048
#define D2H  (2*Hq)       // 1024

// -------- scratch (static device globals; no allocation in kernel_launch) ----
__device__ float d_xW[2][NROWS][G4H];   // [dir][(seq*B+b)*T+t][4H]  (~268 MB)
__device__ float d_Hout[NROWS][D2H];    // bi-LSTM outputs             (64 MB)
__device__ float d_P[NROWS][Cq];        // attention pre-activations   (16 MB)
__device__ float d_hbuf[2][4][Bq][Hq];  // ping-pong hidden state
__device__ float d_cbuf[4][Bq][Hq];     // cell state
__device__ float d_r[2][Bq][D2H];       // pooled representations

// rec: 0=s1 fwd, 1=s2 fwd, 2=s1 bwd, 3=s2 bwd  (seq = rec&1, dir = rec>>1)

__global__ void init_state(const float* s1_h0, const float* s1_c0,
                           const float* s2_h0, const float* s2_c0) {
    int idx = blockIdx.x * blockDim.x + threadIdx.x;
    if (idx >= 4 * Bq * Hq) return;
    int j = idx % Hq;
    int b = (idx / Hq) % Bq;
    int rec = idx / (Hq * Bq);
    int seq = rec & 1, dir = rec >> 1;
    const float* h0 = seq ? s2_h0 : s1_h0;
    const float* c0 = seq ? s2_c0 : s1_c0;
    d_hbuf[0][rec][b][j] = h0[(dir * Bq + b) * Hq + j];
    d_cbuf[rec][b][j]    = c0[(dir * Bq + b) * Hq + j];
}

// ---------------- xW GEMM with fused embedding gather -----------------------
// C[16384, 2048] = emb[tok[row]] (16384 x 300) @ Wih^T (300 x 2048) + bias
__global__ __launch_bounds__(256)
void xw_gemm(const int* __restrict__ s1, const int* __restrict__ s2,
             const float* __restrict__ emb, const float* __restrict__ Wih,
             const float* __restrict__ bias, int dir) {
    __shared__ float sA[64][17];
    __shared__ float sB[64][17];
    __shared__ int   stok[64];
    int tx = threadIdx.x & 15, ty = threadIdx.x >> 4;
    int n0 = blockIdx.x * 64, m0 = blockIdx.y * 64;

    if (threadIdx.x < 64) {
        int m = m0 + threadIdx.x;
        stok[threadIdx.x] = (m < RPS) ? s1[m] : s2[m - RPS];
    }
    float acc[4][4] = {};
    __syncthreads();

    for (int kt = 0; kt < (Eq + 15) / 16; ++kt) {
        int k0 = kt * 16;
#pragma unroll
        for (int i = 0; i < 4; ++i) {
            int e = threadIdx.x + i * 256;
            int r = e >> 4, k = e & 15;
            int kk = k0 + k;
            sA[r][k] = (kk < Eq) ? emb[(long)stok[r] * Eq + kk] : 0.f;
            sB[r][k] = (kk < Eq) ? Wih[(long)(n0 + r) * Eq + kk] : 0.f;
        }
        __syncthreads();
#pragma unroll
        for (int k = 0; k < 16; ++k) {
            float a[4], bb[4];
#pragma unroll
            for (int i = 0; i < 4; ++i) a[i] = sA[ty * 4 + i][k];
#pragma unroll
            for (int j = 0; j < 4; ++j) bb[j] = sB[tx * 4 + j][k];
#pragma unroll
            for (int i = 0; i < 4; ++i)
#pragma unroll
                for (int j = 0; j < 4; ++j) acc[i][j] += a[i] * bb[j];
        }
        __syncthreads();
    }
#pragma unroll
    for (int i = 0; i < 4; ++i)
#pragma unroll
        for (int j = 0; j < 4; ++j) {
            int m = m0 + ty * 4 + i, n = n0 + tx * 4 + j;
            d_xW[dir][m][n] = acc[i][j] + bias[n];
        }
}

// ---------------- fused LSTM step: g = xW + h@Whh^T, gate, update -----------
// grid: (16 col-chunks of 32 H-cols, 8 row-blocks of 32 batch rows); 256 thr.
// Each thread: 4 batch rows x (4 gates of one H-column).
__global__ __launch_bounds__(256)
void lstm_step(int t, int cur,
               const int* __restrict__ s1_len, const int* __restrict__ s2_len,
               const float* __restrict__ Whh_f, const float* __restrict__ Whh_b) {
    __shared__ float sH[32][17];
    __shared__ float sW[128][17];
    int tx = threadIdx.x & 31;   // H-column within chunk
    int ty = threadIdx.x >> 5;   // 0..7, 4 rows each
    int rb  = blockIdx.y;
    int rec = rb >> 1;
    int b0  = (rb & 1) * 32;
    int j0  = blockIdx.x * 32;
    int seq = rec & 1, dir = rec >> 1;
    const float* Whh = dir ? Whh_b : Whh_f;

    float acc[4][4] = {};
    for (int kt = 0; kt < Hq / 16; ++kt) {
        int k0 = kt * 16;
#pragma unroll
        for (int i = 0; i < 2; ++i) {
            int ee = threadIdx.x + i * 256;
            int r = ee >> 4, k = ee & 15;
            sH[r][k] = d_hbuf[cur][rec][b0 + r][k0 + k];
        }
#pragma unroll
        for (int i = 0; i < 8; ++i) {
            int ee = threadIdx.x + i * 256;
            int n = ee >> 4, k = ee & 15;
            int gate = n >> 5, jj = n & 31;
            sW[n][k] = Whh[(long)(gate * Hq + j0 + jj) * Hq + k0 + k];
        }
        __syncthreads();
#pragma unroll
        for (int k = 0; k < 16; ++k) {
            float a[4], w[4];
#pragma unroll
            for (int i = 0; i < 4; ++i) a[i] = sH[ty * 4 + i][k];
#pragma unroll
            for (int g = 0; g < 4; ++g) w[g] = sW[g * 32 + tx][k];
#pragma unroll
            for (int i = 0; i < 4; ++i)
#pragma unroll
                for (int g = 0; g < 4; ++g) acc[i][g] += a[i] * w[g];
        }
        __syncthreads();
    }

    int j = j0 + tx;
    const int* lens = seq ? s2_len : s1_len;
#pragma unroll
    for (int i = 0; i < 4; ++i) {
        int b = b0 + ty * 4 + i;
        int len = lens[b];
        // bwd: at step t consume reversed position idx(b,t); write h back there too
        int tpos = dir ? ((t < len) ? (len - 1 - t) : t) : t;
        long row = (long)(seq * Bq + b) * Tq + tpos;
        float gi = acc[i][0] + d_xW[dir][row][j];
        float gf = acc[i][1] + d_xW[dir][row][Hq + j];
        float gg = acc[i][2] + d_xW[dir][row][2 * Hq + j];
        float go = acc[i][3] + d_xW[dir][row][3 * Hq + j];
        float si = 1.f / (1.f + expf(-gi));
        float sf = 1.f / (1.f + expf(-gf));
        float so = 1.f / (1.f + expf(-go));
        float c  = sf * d_cbuf[rec][b][j] + si * tanhf(gg);
        float h  = so * tanhf(c);
        d_cbuf[rec][b][j]          = c;
        d_hbuf[cur ^ 1][rec][b][j] = h;
        d_Hout[row][dir * Hq + j]  = h;
    }
}

// ---------------- attention projection GEMM: P = Hout @ S1W^T ---------------
__global__ __launch_bounds__(256)
void attn_gemm(const float* __restrict__ S1W) {
    __shared__ float sA[64][17];
    __shared__ float sB[64][17];
    int tx = threadIdx.x & 15, ty = threadIdx.x >> 4;
    int n0 = blockIdx.x * 64, m0 = blockIdx.y * 64;
    float acc[4][4] = {};
    for (int kt = 0; kt < D2H / 16; ++kt) {
        int k0 = kt * 16;
#pragma unroll
        for (int i = 0; i < 4; ++i) {
            int e = threadIdx.x + i * 256;
            int r = e >> 4, k = e & 15;
            sA[r][k] = d_Hout[m0 + r][k0 + k];
            sB[r][k] = S1W[(long)(n0 + r) * D2H + k0 + k];
        }
        __syncthreads();
#pragma unroll
        for (int k = 0; k < 16; ++k) {
            float a[4], bb[4];
#pragma unroll
            for (int i = 0; i < 4; ++i) a[i] = sA[ty * 4 + i][k];
#pragma unroll
            for (int j = 0; j < 4; ++j) bb[j] = sB[tx * 4 + j][k];
#pragma unroll
            for (int i = 0; i < 4; ++i)
#pragma unroll
                for (int j = 0; j < 4; ++j) acc[i][j] += a[i] * bb[j];
        }
        __syncthreads();
    }
#pragma unroll
    for (int i = 0; i < 4; ++i)
#pragma unroll
        for (int j = 0; j < 4; ++j)
            d_P[m0 + ty * 4 + i][n0 + tx * 4 + j] = acc[i][j];
}

// ---------------- masked softmax attention pooling ---------------------------
__global__ __launch_bounds__(128)
void attn_pool(const int* __restrict__ s1_len, const int* __restrict__ s2_len,
               const float* __restrict__ S2W) {
    __shared__ float sS2[Cq];
    __shared__ float ssc[Tq];
    __shared__ float red[Tq];
    int sb = blockIdx.x;            // seq*64 + b
    int seq = sb >> 6, b = sb & 63;
    int t = threadIdx.x;
    for (int c = t; c < Cq; c += Tq) sS2[c] = S2W[c];
    __syncthreads();

    long row = (long)sb * Tq + t;
    float s = 0.f;
    for (int c = 0; c < Cq; ++c) s += tanhf(d_P[row][c]) * sS2[c];
    int len = (seq ? s2_len : s1_len)[b];
    ssc[t] = (t < len) ? s : -1e9f;
    __syncthreads();

    red[t] = ssc[t]; __syncthreads();
    for (int o = 64; o > 0; o >>= 1) { if (t < o) red[t] = fmaxf(red[t], red[t + o]); __syncthreads(); }
    float mx = red[0]; __syncthreads();
    float ex = expf(ssc[t] - mx);
    red[t] = ex; __syncthreads();
    for (int o = 64; o > 0; o >>= 1) { if (t < o) red[t] += red[t + o]; __syncthreads(); }
    float inv = 1.f / red[0];
    __syncthreads();
    ssc[t] = ex * inv;
    __syncthreads();

    long rowbase = (long)sb * Tq;
    for (int d = t; d < D2H; d += Tq) {
        float acc = 0.f;
        for (int tt = 0; tt < Tq; ++tt) acc += ssc[tt] * d_Hout[rowbase + tt][d];
        d_r[seq][b][d] = acc;
    }
}

// ---------------- final MLP head + sigmoid ----------------------------------
__global__ __launch_bounds__(512)
void final_mlp(const float* __restrict__ mlpW, const float* __restrict__ mlpb,
               const float* __restrict__ outW, const float* __restrict__ outb,
               float* __restrict__ out) {
    __shared__ float merged[4 * Hq];   // 2048
    __shared__ float smlp[Mq];
    __shared__ float red[16];
    int b = blockIdx.x;
    int tid = threadIdx.x;

    for (int d = tid; d < 2 * D2H; d += Mq) {
        float v;
        if (d < D2H) v = d_r[0][b][d] + d_r[1][b][d];
        else { float df = d_r[0][b][d - D2H] - d_r[1][b][d - D2H]; v = df * df; }
        merged[d] = v;
    }
    __syncthreads();

    int warp = tid >> 5, lane = tid & 31;
    for (int m = warp * 32; m < warp * 32 + 32; ++m) {
        float p = 0.f;
        for (int d = lane; d < 4 * Hq; d += 32) p += merged[d] * mlpW[(long)m * 4 * Hq + d];
        for (int o = 16; o > 0; o >>= 1) p += __shfl_down_sync(0xffffffff, p, o);
        if (lane == 0) smlp[m] = p + mlpb[m];
    }
    __syncthreads();

    float p = smlp[tid] * outW[tid];
    for (int o = 16; o > 0; o >>= 1) p += __shfl_down_sync(0xffffffff, p, o);
    if (lane == 0) red[warp] = p;
    __syncthreads();
    if (tid == 0) {
        float l = outb[0];
        for (int w = 0; w < 16; ++w) l += red[w];
        out[b] = 1.f / (1.f + expf(-l));
    }
}

// ---------------- launch ------------------------------------------------------
extern "C" void kernel_launch(void* const* d_in, const int* in_sizes, int n_in,
                              void* d_out, int out_size) {
    const int*   s1     = (const int*)d_in[0];
    const int*   s2     = (const int*)d_in[1];
    const int*   s1_len = (const int*)d_in[2];
    const int*   s2_len = (const int*)d_in[3];
    const float* s1_h0  = (const float*)d_in[4];
    const float* s1_c0  = (const float*)d_in[5];
    const float* s2_h0  = (const float*)d_in[6];
    const float* s2_c0  = (const float*)d_in[7];
    const float* emb    = (const float*)d_in[8];
    const float* Wih_f  = (const float*)d_in[9];
    const float* Whh_f  = (const float*)d_in[10];
    const float* b_f    = (const float*)d_in[11];
    const float* Wih_b  = (const float*)d_in[12];
    const float* Whh_b  = (const float*)d_in[13];
    const float* b_b    = (const float*)d_in[14];
    const float* S1W    = (const float*)d_in[15];
    const float* S2W    = (const float*)d_in[16];
    const float* mlpW   = (const float*)d_in[17];
    const float* mlpb   = (const float*)d_in[18];
    const float* outW   = (const float*)d_in[19];
    const float* outb   = (const float*)d_in[20];
    float* out = (float*)d_out;

    init_state<<<(4 * Bq * Hq + 255) / 256, 256>>>(s1_h0, s1_c0, s2_h0, s2_c0);

    dim3 gx(G4H / 64, NROWS / 64);   // (32, 256)
    xw_gemm<<<gx, 256>>>(s1, s2, emb, Wih_f, b_f, 0);
    xw_gemm<<<gx, 256>>>(s1, s2, emb, Wih_b, b_b, 1);

    for (int t = 0; t < Tq; ++t)
        lstm_step<<<dim3(16, 8), 256>>>(t, t & 1, s1_len, s2_len, Whh_f, Whh_b);

    attn_gemm<<<dim3(Cq / 64, NROWS / 64), 256>>>(S1W);   // (4, 256)
    attn_pool<<<128, 128>>>(s1_len, s2_len, S2W);
    final_mlp<<<Bq, 512>>>(mlpW, mlpb, outW, outb, out);
}

// round 5
// speedup vs baseline: 1.3259x; 1.3259x over previous
#include <cuda_runtime.h>
#include <cuda_bf16.h>
#include <stdint.h>
#include <math.h>

// Problem constants
#define Bq   64
#define Tq   128
#define Eq   300
#define Hq   512
#define Cq   256
#define Mq   512
#define RPS  (Bq*Tq)      // rows per sequence: 8192
#define NROWS (2*RPS)     // 16384
#define G4H  (4*Hq)       // 2048
#define D2H  (2*Hq)       // 1024
#define NCTA 128          // persistent LSTM grid
#define KPAD 520          // padded K stride for smem weights (bank-conflict-free)

// -------- scratch (static device globals; no allocation anywhere) -----------
__device__ float d_xW[2][NROWS][G4H];    // [dir][(seq*B+b)*T+t][4H]
__device__ float d_Hout[NROWS][D2H];     // bi-LSTM outputs
__device__ float d_P[NROWS][Cq];         // attention pre-activations
__device__ float d_r[2][Bq][D2H];        // pooled representations
__device__ __nv_bfloat16 d_Wb16[2][2][G4H][Hq];      // [dir][hi/lo][n][k]
__device__ __nv_bfloat16 d_h16[2][2][2][128][Hq];    // [parity][hi/lo][dir][m][k]
__device__ unsigned g_cnt;
__device__ unsigned g_epoch;

// rec: 0=s1 fwd, 1=s2 fwd, 2=s1 bwd, 3=s2 bwd.  Within a dir: m = seq*64 + b.

// ---------------- init: reset barrier, seed h16 from h0 ---------------------
__global__ void init_state(const float* s1_h0, const float* s2_h0) {
    int idx = blockIdx.x * blockDim.x + threadIdx.x;
    if (idx == 0) { g_cnt = 0; g_epoch = 0; }
    if (idx >= 2 * 128 * Hq) return;
    int j   = idx % Hq;
    int m   = (idx / Hq) % 128;
    int dir = idx / (Hq * 128);
    int seq = m >> 6, b = m & 63;
    float h = (seq ? s2_h0 : s1_h0)[(dir * Bq + b) * Hq + j];
    __nv_bfloat16 hh = __float2bfloat16(h);
    __nv_bfloat16 hl = __float2bfloat16(h - __bfloat162float(hh));
    d_h16[0][0][dir][m][j] = hh;
    d_h16[0][1][dir][m][j] = hl;
}

// ---------------- split Whh into bf16 hi/lo ----------------------------------
__global__ void prep_weights(const float* __restrict__ Whh_f,
                             const float* __restrict__ Whh_b) {
    int idx = blockIdx.x * blockDim.x + threadIdx.x;
    if (idx >= 2 * G4H * Hq) return;
    int dir = idx / (G4H * Hq);
    int r   = idx % (G4H * Hq);
    float w = (dir ? Whh_b : Whh_f)[r];
    __nv_bfloat16 hi = __float2bfloat16(w);
    __nv_bfloat16 lo = __float2bfloat16(w - __bfloat162float(hi));
    int n = r / Hq, k = r % Hq;
    d_Wb16[dir][0][n][k] = hi;
    d_Wb16[dir][1][n][k] = lo;
}

// ---------------- xW GEMM with fused embedding gather ------------------------
__global__ __launch_bounds__(256)
void xw_gemm(const int* __restrict__ s1, const int* __restrict__ s2,
             const float* __restrict__ emb, const float* __restrict__ Wih,
             const float* __restrict__ bias, int dir) {
    __shared__ float sA[64][17];
    __shared__ float sB[64][17];
    __shared__ int   stok[64];
    int tx = threadIdx.x & 15, ty = threadIdx.x >> 4;
    int n0 = blockIdx.x * 64, m0 = blockIdx.y * 64;

    if (threadIdx.x < 64) {
        int m = m0 + threadIdx.x;
        stok[threadIdx.x] = (m < RPS) ? s1[m] : s2[m - RPS];
    }
    float acc[4][4] = {};
    __syncthreads();

    for (int kt = 0; kt < (Eq + 15) / 16; ++kt) {
        int k0 = kt * 16;
#pragma unroll
        for (int i = 0; i < 4; ++i) {
            int e = threadIdx.x + i * 256;
            int r = e >> 4, k = e & 15;
            int kk = k0 + k;
            sA[r][k] = (kk < Eq) ? emb[(long)stok[r] * Eq + kk] : 0.f;
            sB[r][k] = (kk < Eq) ? Wih[(long)(n0 + r) * Eq + kk] : 0.f;
        }
        __syncthreads();
#pragma unroll
        for (int k = 0; k < 16; ++k) {
            float a[4], bb[4];
#pragma unroll
            for (int i = 0; i < 4; ++i) a[i] = sA[ty * 4 + i][k];
#pragma unroll
            for (int j = 0; j < 4; ++j) bb[j] = sB[tx * 4 + j][k];
#pragma unroll
            for (int i = 0; i < 4; ++i)
#pragma unroll
                for (int j = 0; j < 4; ++j) acc[i][j] += a[i] * bb[j];
        }
        __syncthreads();
    }
#pragma unroll
    for (int i = 0; i < 4; ++i)
#pragma unroll
        for (int j = 0; j < 4; ++j) {
            int m = m0 + ty * 4 + i, n = n0 + tx * 4 + j;
            d_xW[dir][m][n] = acc[i][j] + bias[n];
        }
}

// ---------------- mma.sync bf16 helper ---------------------------------------
__device__ __forceinline__ void mma_bf16(float* d, const uint32_t* a, const uint32_t* b) {
    asm volatile(
        "mma.sync.aligned.m16n8k16.row.col.f32.bf16.bf16.f32 "
        "{%0,%1,%2,%3}, {%4,%5,%6,%7}, {%8,%9}, {%0,%1,%2,%3};\n"
        : "+f"(d[0]), "+f"(d[1]), "+f"(d[2]), "+f"(d[3])
        : "r"(a[0]), "r"(a[1]), "r"(a[2]), "r"(a[3]),
          "r"(b[0]), "r"(b[1]));
}

// ---------------- persistent LSTM: all 128 steps, tensor cores --------------
// Grid: 128 CTAs. CTA = (dir = bid&1, j-chunk of 8 H-cols). 256 threads.
// Each warp: 16 M-rows (of 128 = 2 seqs x 64 batch) x 32 N-cols (4 gates x 8).
// Whh slice (hi+lo) persistent in smem; cell state c in registers.
__global__ __launch_bounds__(256)
void lstm_persist(const int* __restrict__ s1_len, const int* __restrict__ s2_len,
                  const float* __restrict__ s1_c0, const float* __restrict__ s2_c0) {
    extern __shared__ __nv_bfloat16 sW[];   // [2 split][4 gate][8 jj][KPAD]
    const int tid  = threadIdx.x;
    const int lane = tid & 31;
    const int warp = tid >> 5;
    const int dir  = blockIdx.x & 1;
    const int j0   = (blockIdx.x >> 1) * 8;

    // ---- load weight slice into smem (once) ----
    for (int i = tid; i < 64 * (Hq / 2); i += 256) {    // u32 granules
        int row = i >> 8;            // 0..63 : s*32 + g*8 + jj
        int kk  = (i & 255) * 2;
        int s = row >> 5, g = (row >> 3) & 3, jj = row & 7;
        *(uint32_t*)&sW[row * KPAD + kk] =
            *(const uint32_t*)&d_Wb16[dir][s][g * Hq + j0 + jj][kk];
    }

    // ---- per-thread ownership ----
    const int m0  = warp * 16;          // warp's row base
    const int seq = m0 >> 6;            // warps 0-3: seq0, 4-7: seq1
    const int r0  = m0 + (lane >> 2);   // rows r0 and r0+8
    const int c0j = j0 + (lane & 3) * 2;  // cols c0j, c0j+1
    const int*   lens = seq ? s2_len : s1_len;
    const float* c0p  = seq ? s2_c0  : s1_c0;
    const int b0 = r0 & 63;
    int len_[2] = { lens[b0], lens[b0 + 8] };

    // cell state in registers: [ri*2+ci] = (row r0+8*ri, col c0j+ci)
    float creg[4];
#pragma unroll
    for (int ri = 0; ri < 2; ++ri)
#pragma unroll
        for (int ci = 0; ci < 2; ++ci)
            creg[ri * 2 + ci] = c0p[(dir * Bq + b0 + 8 * ri) * Hq + c0j + ci];

    __syncthreads();

    const int oA = (r0 * Hq + (lane & 3) * 2) >> 1;   // u32 index into h slab
    unsigned myep = 0;

    for (int t = 0; t < Tq; ++t) {
        const int p = t & 1;
        const uint32_t* Hhi = (const uint32_t*)&d_h16[p][0][dir][0][0];
        const uint32_t* Hlo = (const uint32_t*)&d_h16[p][1][dir][0][0];

        float acc[4][4] = {};
        uint32_t aH[2][4], aL[2][4];

        // prefetch k-tile 0 (L2-only loads: fresh across the grid barrier)
        {
            int o = oA;
            aH[0][0] = __ldcg(Hhi + o);        aH[0][1] = __ldcg(Hhi + o + 2048);
            aH[0][2] = __ldcg(Hhi + o + 4);    aH[0][3] = __ldcg(Hhi + o + 2052);
            aL[0][0] = __ldcg(Hlo + o);        aL[0][1] = __ldcg(Hlo + o + 2048);
            aL[0][2] = __ldcg(Hlo + o + 4);    aL[0][3] = __ldcg(Hlo + o + 2052);
        }

#pragma unroll 4
        for (int kt = 0; kt < 32; ++kt) {
            const int cur = kt & 1;
            if (kt < 31) {
                int o = oA + (kt + 1) * 8;
                aH[cur ^ 1][0] = __ldcg(Hhi + o);       aH[cur ^ 1][1] = __ldcg(Hhi + o + 2048);
                aH[cur ^ 1][2] = __ldcg(Hhi + o + 4);   aH[cur ^ 1][3] = __ldcg(Hhi + o + 2052);
                aL[cur ^ 1][0] = __ldcg(Hlo + o);       aL[cur ^ 1][1] = __ldcg(Hlo + o + 2048);
                aL[cur ^ 1][2] = __ldcg(Hlo + o + 4);   aL[cur ^ 1][3] = __ldcg(Hlo + o + 2052);
            }
            const int kb   = kt * 16 + (lane & 3) * 2;
            const int nrow = lane >> 2;
#pragma unroll
            for (int g = 0; g < 4; ++g) {
                uint32_t bh[2], bl[2];
                const __nv_bfloat16* ph = &sW[(g * 8 + nrow) * KPAD + kb];
                const __nv_bfloat16* pl = &sW[(32 + g * 8 + nrow) * KPAD + kb];  // lo rows start at row 32
                bh[0] = *(const uint32_t*)ph;  bh[1] = *(const uint32_t*)(ph + 8);
                bl[0] = *(const uint32_t*)pl;  bl[1] = *(const uint32_t*)(pl + 8);
                mma_bf16(acc[g], aH[cur], bh);   // hi*hi
                mma_bf16(acc[g], aL[cur], bh);   // lo*hi
                mma_bf16(acc[g], aH[cur], bl);   // hi*lo
            }
        }

        // ---- epilogue: gates, cell/h update, publish h ----
#pragma unroll
        for (int ri = 0; ri < 2; ++ri) {
            const int m   = r0 + ri * 8;
            const int b   = b0 + ri * 8;
            const int len = len_[ri];
            const int tpos = dir ? ((t < len) ? (len - 1 - t) : t) : t;
            const int rowx = (seq * Bq + b) * Tq + tpos;
            const float* xwr = &d_xW[dir][rowx][0];
            const float2 gi2 = *(const float2*)&xwr[c0j];
            const float2 gf2 = *(const float2*)&xwr[Hq + c0j];
            const float2 gg2 = *(const float2*)&xwr[2 * Hq + c0j];
            const float2 go2 = *(const float2*)&xwr[3 * Hq + c0j];
#pragma unroll
            for (int ci = 0; ci < 2; ++ci) {
                const int ai = ri * 2 + ci;
                float gi = acc[0][ai] + (ci ? gi2.y : gi2.x);
                float gf = acc[1][ai] + (ci ? gf2.y : gf2.x);
                float gg = acc[2][ai] + (ci ? gg2.y : gg2.x);
                float go = acc[3][ai] + (ci ? go2.y : go2.x);
                float si = 1.f / (1.f + expf(-gi));
                float sf = 1.f / (1.f + expf(-gf));
                float so = 1.f / (1.f + expf(-go));
                float c  = sf * creg[ai] + si * tanhf(gg);
                float h  = so * tanhf(c);
                creg[ai] = c;
                d_Hout[rowx][dir * Hq + c0j + ci] = h;
                __nv_bfloat16 hh = __float2bfloat16(h);
                __nv_bfloat16 hl = __float2bfloat16(h - __bfloat162float(hh));
                d_h16[p ^ 1][0][dir][m][c0j + ci] = hh;
                d_h16[p ^ 1][1][dir][m][c0j + ci] = hl;
            }
        }

        // ---- grid barrier (sense via monotonically increasing epoch) ----
        __syncthreads();
        if (tid == 0) {
            __threadfence();                       // publish h stores
            unsigned arrived = atomicAdd(&g_cnt, 1);
            if (arrived == NCTA - 1) {
                g_cnt = 0;
                __threadfence();
                atomicExch(&g_epoch, myep + 1);    // release
            } else {
                while (*(volatile unsigned*)&g_epoch <= myep) { }
            }
            __threadfence();                       // acquire (flush L1)
        }
        myep++;
        __syncthreads();
    }
}

// ---------------- attention projection GEMM: P = Hout @ S1W^T ---------------
__global__ __launch_bounds__(256)
void attn_gemm(const float* __restrict__ S1W) {
    __shared__ float sA[64][17];
    __shared__ float sB[64][17];
    int tx = threadIdx.x & 15, ty = threadIdx.x >> 4;
    int n0 = blockIdx.x * 64, m0 = blockIdx.y * 64;
    float acc[4][4] = {};
    for (int kt = 0; kt < D2H / 16; ++kt) {
        int k0 = kt * 16;
#pragma unroll
        for (int i = 0; i < 4; ++i) {
            int e = threadIdx.x + i * 256;
            int r = e >> 4, k = e & 15;
            sA[r][k] = d_Hout[m0 + r][k0 + k];
            sB[r][k] = S1W[(long)(n0 + r) * D2H + k0 + k];
        }
        __syncthreads();
#pragma unroll
        for (int k = 0; k < 16; ++k) {
            float a[4], bb[4];
#pragma unroll
            for (int i = 0; i < 4; ++i) a[i] = sA[ty * 4 + i][k];
#pragma unroll
            for (int j = 0; j < 4; ++j) bb[j] = sB[tx * 4 + j][k];
#pragma unroll
            for (int i = 0; i < 4; ++i)
#pragma unroll
                for (int j = 0; j < 4; ++j) acc[i][j] += a[i] * bb[j];
        }
        __syncthreads();
    }
#pragma unroll
    for (int i = 0; i < 4; ++i)
#pragma unroll
        for (int j = 0; j < 4; ++j)
            d_P[m0 + ty * 4 + i][n0 + tx * 4 + j] = acc[i][j];
}

// ---------------- masked softmax attention pooling ---------------------------
__global__ __launch_bounds__(128)
void attn_pool(const int* __restrict__ s1_len, const int* __restrict__ s2_len,
               const float* __restrict__ S2W) {
    __shared__ float sS2[Cq];
    __shared__ float ssc[Tq];
    __shared__ float red[Tq];
    int sb = blockIdx.x;            // seq*64 + b
    int seq = sb >> 6, b = sb & 63;
    int t = threadIdx.x;
    for (int c = t; c < Cq; c += Tq) sS2[c] = S2W[c];
    __syncthreads();

    long row = (long)sb * Tq + t;
    float s = 0.f;
    for (int c = 0; c < Cq; ++c) s += tanhf(d_P[row][c]) * sS2[c];
    int len = (seq ? s2_len : s1_len)[b];
    ssc[t] = (t < len) ? s : -1e9f;
    __syncthreads();

    red[t] = ssc[t]; __syncthreads();
    for (int o = 64; o > 0; o >>= 1) { if (t < o) red[t] = fmaxf(red[t], red[t + o]); __syncthreads(); }
    float mx = red[0]; __syncthreads();
    float ex = expf(ssc[t] - mx);
    red[t] = ex; __syncthreads();
    for (int o = 64; o > 0; o >>= 1) { if (t < o) red[t] += red[t + o]; __syncthreads(); }
    float inv = 1.f / red[0];
    __syncthreads();
    ssc[t] = ex * inv;
    __syncthreads();

    long rowbase = (long)sb * Tq;
    for (int d = t; d < D2H; d += Tq) {
        float acc = 0.f;
        for (int tt = 0; tt < Tq; ++tt) acc += ssc[tt] * d_Hout[rowbase + tt][d];
        d_r[seq][b][d] = acc;
    }
}

// ---------------- final MLP head + sigmoid ----------------------------------
__global__ __launch_bounds__(512)
void final_mlp(const float* __restrict__ mlpW, const float* __restrict__ mlpb,
               const float* __restrict__ outW, const float* __restrict__ outb,
               float* __restrict__ out) {
    __shared__ float merged[4 * Hq];   // 2048
    __shared__ float smlp[Mq];
    __shared__ float red[16];
    int b = blockIdx.x;
    int tid = threadIdx.x;

    for (int d = tid; d < 2 * D2H; d += Mq) {
        float v;
        if (d < D2H) v = d_r[0][b][d] + d_r[1][b][d];
        else { float df = d_r[0][b][d - D2H] - d_r[1][b][d - D2H]; v = df * df; }
        merged[d] = v;
    }
    __syncthreads();

    int warp = tid >> 5, lane = tid & 31;
    for (int m = warp * 32; m < warp * 32 + 32; ++m) {
        float p = 0.f;
        for (int d = lane; d < 4 * Hq; d += 32) p += merged[d] * mlpW[(long)m * 4 * Hq + d];
        for (int o = 16; o > 0; o >>= 1) p += __shfl_down_sync(0xffffffff, p, o);
        if (lane == 0) smlp[m] = p + mlpb[m];
    }
    __syncthreads();

    float p = smlp[tid] * outW[tid];
    for (int o = 16; o > 0; o >>= 1) p += __shfl_down_sync(0xffffffff, p, o);
    if (lane == 0) red[warp] = p;
    __syncthreads();
    if (tid == 0) {
        float l = outb[0];
        for (int w = 0; w < 16; ++w) l += red[w];
        out[b] = 1.f / (1.f + expf(-l));
    }
}

// ---------------- launch ------------------------------------------------------
extern "C" void kernel_launch(void* const* d_in, const int* in_sizes, int n_in,
                              void* d_out, int out_size) {
    const int*   s1     = (const int*)d_in[0];
    const int*   s2     = (const int*)d_in[1];
    const int*   s1_len = (const int*)d_in[2];
    const int*   s2_len = (const int*)d_in[3];
    const float* s1_h0  = (const float*)d_in[4];
    const float* s1_c0  = (const float*)d_in[5];
    const float* s2_h0  = (const float*)d_in[6];
    const float* s2_c0  = (const float*)d_in[7];
    const float* emb    = (const float*)d_in[8];
    const float* Wih_f  = (const float*)d_in[9];
    const float* Whh_f  = (const float*)d_in[10];
    const float* b_f    = (const float*)d_in[11];
    const float* Wih_b  = (const float*)d_in[12];
    const float* Whh_b  = (const float*)d_in[13];
    const float* b_b    = (const float*)d_in[14];
    const float* S1W    = (const float*)d_in[15];
    const float* S2W    = (const float*)d_in[16];
    const float* mlpW   = (const float*)d_in[17];
    const float* mlpb   = (const float*)d_in[18];
    const float* outW   = (const float*)d_in[19];
    const float* outb   = (const float*)d_in[20];
    float* out = (float*)d_out;

    const int smem_lstm = 2 * 4 * 8 * KPAD * (int)sizeof(__nv_bfloat16);  // 66560
    cudaFuncSetAttribute(lstm_persist, cudaFuncAttributeMaxDynamicSharedMemorySize, smem_lstm);

    init_state<<<(2 * 128 * Hq + 255) / 256, 256>>>(s1_h0, s2_h0);
    prep_weights<<<(2 * G4H * Hq + 255) / 256, 256>>>(Whh_f, Whh_b);

    dim3 gx(G4H / 64, NROWS / 64);   // (32, 256)
    xw_gemm<<<gx, 256>>>(s1, s2, emb, Wih_f, b_f, 0);
    xw_gemm<<<gx, 256>>>(s1, s2, emb, Wih_b, b_b, 1);

    lstm_persist<<<NCTA, 256, smem_lstm>>>(s1_len, s2_len, s1_c0, s2_c0);

    attn_gemm<<<dim3(Cq / 64, NROWS / 64), 256>>>(S1W);   // (4, 256)
    attn_pool<<<128, 128>>>(s1_len, s2_len, S2W);
    final_mlp<<<Bq, 512>>>(mlpW, mlpb, outW, outb, out);
}

// round 6
// speedup vs baseline: 1.7918x; 1.3514x over previous
#include <cuda_runtime.h>
#include <cuda_bf16.h>
#include <stdint.h>
#include <math.h>

// Problem constants
#define Bq   64
#define Tq   128
#define Eq   300
#define Hq   512
#define Cq   256
#define Mq   512
#define RPS  (Bq*Tq)      // rows per sequence: 8192
#define NROWS (2*RPS)     // 16384
#define G4H  (4*Hq)       // 2048
#define D2H  (2*Hq)       // 1024
#define NCTA 128          // persistent LSTM grid
#define KPAD 520          // padded K stride for smem weights
#define KE   304          // Eq padded to multiple of 16

// -------- scratch (static device globals; no allocation anywhere) -----------
__device__ float d_xW[2][NROWS][G4H];    // [dir][(seq*B+b)*T+t][4H]
__device__ float d_Hout[NROWS][D2H];     // bi-LSTM outputs (fp32, for attn_pool)
__device__ float d_P[NROWS][Cq];         // attention pre-activations
__device__ float d_r[2][Bq][D2H];        // pooled representations
__device__ __nv_bfloat16 d_Wb16[2][2][G4H][Hq];      // [dir][hi/lo][n][k]  Whh
__device__ __nv_bfloat16 d_h16[2][2][2][128][Hq];    // [parity][hi/lo][dir][m][k]
__device__ __nv_bfloat16 d_x16[2][NROWS][KE];        // [hi/lo] gathered embeddings
__device__ __nv_bfloat16 d_W16[2][2*G4H][KE];        // [hi/lo][dir*2048+n][k] Wih
__device__ float d_biasC[2*G4H];                     // combined Wih bias
__device__ __nv_bfloat16 d_Ho16[2][NROWS][D2H];      // [hi/lo] bf16 Hout
__device__ __nv_bfloat16 d_S1W16[2][Cq][D2H];        // [hi/lo] S1W
__device__ unsigned g_cnt;
__device__ unsigned g_epoch;

// ---------------- init: reset barrier, seed h16 from h0 ---------------------
__global__ void init_state(const float* s1_h0, const float* s2_h0) {
    int idx = blockIdx.x * blockDim.x + threadIdx.x;
    if (idx == 0) { g_cnt = 0; g_epoch = 0; }
    if (idx >= 2 * 128 * Hq) return;
    int j   = idx % Hq;
    int m   = (idx / Hq) % 128;
    int dir = idx / (Hq * 128);
    int seq = m >> 6, b = m & 63;
    float h = (seq ? s2_h0 : s1_h0)[(dir * Bq + b) * Hq + j];
    __nv_bfloat16 hh = __float2bfloat16(h);
    __nv_bfloat16 hl = __float2bfloat16(h - __bfloat162float(hh));
    d_h16[0][0][dir][m][j] = hh;
    d_h16[0][1][dir][m][j] = hl;
}

// ---------------- split Whh into bf16 hi/lo ----------------------------------
__global__ void prep_weights(const float* __restrict__ Whh_f,
                             const float* __restrict__ Whh_b) {
    int idx = blockIdx.x * blockDim.x + threadIdx.x;
    if (idx >= 2 * G4H * Hq) return;
    int dir = idx / (G4H * Hq);
    int r   = idx % (G4H * Hq);
    float w = (dir ? Whh_b : Whh_f)[r];
    __nv_bfloat16 hi = __float2bfloat16(w);
    __nv_bfloat16 lo = __float2bfloat16(w - __bfloat162float(hi));
    int n = r / Hq, k = r % Hq;
    d_Wb16[dir][0][n][k] = hi;
    d_Wb16[dir][1][n][k] = lo;
}

// ---------------- gather tokens + convert emb rows to bf16 hi/lo -------------
__global__ void gather_convert(const int* __restrict__ s1, const int* __restrict__ s2,
                               const float* __restrict__ emb) {
    int idx = blockIdx.x * blockDim.x + threadIdx.x;
    if (idx >= NROWS * KE) return;
    int m = idx / KE, k = idx % KE;
    int tok = (m < RPS) ? s1[m] : s2[m - RPS];
    float v = (k < Eq) ? emb[(long)tok * Eq + k] : 0.f;
    __nv_bfloat16 hi = __float2bfloat16(v);
    d_x16[0][m][k] = hi;
    d_x16[1][m][k] = __float2bfloat16(v - __bfloat162float(hi));
}

// ---------------- convert Wih (both dirs) to bf16 hi/lo + combined bias ------
__global__ void convert_wih(const float* __restrict__ Wih_f, const float* __restrict__ Wih_b,
                            const float* __restrict__ b_f, const float* __restrict__ b_b) {
    int idx = blockIdx.x * blockDim.x + threadIdx.x;
    if (idx >= 2 * G4H * KE) return;
    int n = idx / KE, k = idx % KE;
    int dir = n >> 11, nn = n & 2047;
    const float* W = dir ? Wih_b : Wih_f;
    float v = (k < Eq) ? W[(long)nn * Eq + k] : 0.f;
    __nv_bfloat16 hi = __float2bfloat16(v);
    d_W16[0][n][k] = hi;
    d_W16[1][n][k] = __float2bfloat16(v - __bfloat162float(hi));
    if (k == 0) d_biasC[n] = (dir ? b_b : b_f)[nn];
}

// ---------------- convert S1W to bf16 hi/lo -----------------------------------
__global__ void convert_s1w(const float* __restrict__ S1W) {
    int idx = blockIdx.x * blockDim.x + threadIdx.x;
    if (idx >= Cq * D2H) return;
    float v = S1W[idx];
    int c = idx / D2H, k = idx % D2H;
    __nv_bfloat16 hi = __float2bfloat16(v);
    d_S1W16[0][c][k] = hi;
    d_S1W16[1][c][k] = __float2bfloat16(v - __bfloat162float(hi));
}

// ---------------- mma.sync bf16 helper ---------------------------------------
__device__ __forceinline__ void mma_bf16(float* d, const uint32_t* a, const uint32_t* b) {
    asm volatile(
        "mma.sync.aligned.m16n8k16.row.col.f32.bf16.bf16.f32 "
        "{%0,%1,%2,%3}, {%4,%5,%6,%7}, {%8,%9}, {%0,%1,%2,%3};\n"
        : "+f"(d[0]), "+f"(d[1]), "+f"(d[2]), "+f"(d[3])
        : "r"(a[0]), "r"(a[1]), "r"(a[2]), "r"(a[3]),
          "r"(b[0]), "r"(b[1]));
}

// ---------------- xW via tensor cores: [16384,304] @ [304,4096] --------------
// CTA 64(M) x 256(N), 8 warps (2 M x 4 N), warp tile 32x64. grid (16, 256).
__global__ __launch_bounds__(256)
void xw_mma() {
    const int lane = threadIdx.x & 31;
    const int warp = threadIdx.x >> 5;
    const int wm = warp & 1, wn = warp >> 1;
    const int m0 = blockIdx.y * 64 + wm * 32;
    const int n0 = blockIdx.x * 256 + wn * 64;
    const int RS = KE / 2;                 // u32 row stride (152)
    const int kc = lane & 3;
    const int rr = lane >> 2;

    const uint32_t* Xhi = (const uint32_t*)&d_x16[0][0][0];
    const uint32_t* Xlo = (const uint32_t*)&d_x16[1][0][0];
    const uint32_t* Whi = (const uint32_t*)&d_W16[0][0][0];
    const uint32_t* Wlo = (const uint32_t*)&d_W16[1][0][0];

    float acc[2][8][4] = {};

    for (int kt = 0; kt < KE / 16; ++kt) {
        const int k0 = kt * 8;             // u32 per kstep
        uint32_t aH[2][4], aL[2][4];
#pragma unroll
        for (int mt = 0; mt < 2; ++mt) {
            int base = (m0 + mt * 16 + rr) * RS + k0 + kc;
            aH[mt][0] = Xhi[base];          aH[mt][1] = Xhi[base + 8 * RS];
            aH[mt][2] = Xhi[base + 4];      aH[mt][3] = Xhi[base + 8 * RS + 4];
            aL[mt][0] = Xlo[base];          aL[mt][1] = Xlo[base + 8 * RS];
            aL[mt][2] = Xlo[base + 4];      aL[mt][3] = Xlo[base + 8 * RS + 4];
        }
#pragma unroll
        for (int nt = 0; nt < 8; ++nt) {
            int bb = (n0 + nt * 8 + rr) * RS + k0 + kc;
            uint32_t bh[2] = { Whi[bb], Whi[bb + 4] };
            uint32_t bl[2] = { Wlo[bb], Wlo[bb + 4] };
#pragma unroll
            for (int mt = 0; mt < 2; ++mt) {
                mma_bf16(acc[mt][nt], aH[mt], bh);
                mma_bf16(acc[mt][nt], aL[mt], bh);
                mma_bf16(acc[mt][nt], aH[mt], bl);
            }
        }
    }
    // D frag: d0=(r,c), d1=(r,c+1), d2=(r+8,c), d3=(r+8,c+1)
#pragma unroll
    for (int mt = 0; mt < 2; ++mt)
#pragma unroll
        for (int nt = 0; nt < 8; ++nt) {
            int r  = m0 + mt * 16 + rr;
            int cc = n0 + nt * 8 + (lane & 3) * 2;
#pragma unroll
            for (int i = 0; i < 4; ++i) {
                int m = r + (i >> 1) * 8;
                int n = cc + (i & 1);
                int dir = n >> 11, nn = n & 2047;
                d_xW[dir][m][nn] = acc[mt][nt][i] + d_biasC[n];
            }
        }
}

// ---------------- persistent LSTM: all 128 steps, tensor cores ---------------
__global__ __launch_bounds__(256)
void lstm_persist(const int* __restrict__ s1_len, const int* __restrict__ s2_len,
                  const float* __restrict__ s1_c0, const float* __restrict__ s2_c0) {
    extern __shared__ __nv_bfloat16 sW[];   // [2 split][4 gate][8 jj][KPAD]
    const int tid  = threadIdx.x;
    const int lane = tid & 31;
    const int warp = tid >> 5;
    const int dir  = blockIdx.x & 1;
    const int j0   = (blockIdx.x >> 1) * 8;

    for (int i = tid; i < 64 * (Hq / 2); i += 256) {
        int row = i >> 8;
        int kk  = (i & 255) * 2;
        int s = row >> 5, g = (row >> 3) & 3, jj = row & 7;
        *(uint32_t*)&sW[row * KPAD + kk] =
            *(const uint32_t*)&d_Wb16[dir][s][g * Hq + j0 + jj][kk];
    }

    const int m0  = warp * 16;
    const int seq = m0 >> 6;
    const int r0  = m0 + (lane >> 2);
    const int c0j = j0 + (lane & 3) * 2;
    const int*   lens = seq ? s2_len : s1_len;
    const float* c0p  = seq ? s2_c0  : s1_c0;
    const int b0 = r0 & 63;
    int len_[2] = { lens[b0], lens[b0 + 8] };

    float creg[4];
#pragma unroll
    for (int ri = 0; ri < 2; ++ri)
#pragma unroll
        for (int ci = 0; ci < 2; ++ci)
            creg[ri * 2 + ci] = c0p[(dir * Bq + b0 + 8 * ri) * Hq + c0j + ci];

    __syncthreads();

    const int oA = (r0 * Hq + (lane & 3) * 2) >> 1;
    unsigned myep = 0;

    for (int t = 0; t < Tq; ++t) {
        const int p = t & 1;
        const uint32_t* Hhi = (const uint32_t*)&d_h16[p][0][dir][0][0];
        const uint32_t* Hlo = (const uint32_t*)&d_h16[p][1][dir][0][0];

        float acc[4][4] = {};
        uint32_t aH[2][4], aL[2][4];

        {
            int o = oA;
            aH[0][0] = __ldcg(Hhi + o);        aH[0][1] = __ldcg(Hhi + o + 2048);
            aH[0][2] = __ldcg(Hhi + o + 4);    aH[0][3] = __ldcg(Hhi + o + 2052);
            aL[0][0] = __ldcg(Hlo + o);        aL[0][1] = __ldcg(Hlo + o + 2048);
            aL[0][2] = __ldcg(Hlo + o + 4);    aL[0][3] = __ldcg(Hlo + o + 2052);
        }

#pragma unroll 4
        for (int kt = 0; kt < 32; ++kt) {
            const int cur = kt & 1;
            if (kt < 31) {
                int o = oA + (kt + 1) * 8;
                aH[cur ^ 1][0] = __ldcg(Hhi + o);       aH[cur ^ 1][1] = __ldcg(Hhi + o + 2048);
                aH[cur ^ 1][2] = __ldcg(Hhi + o + 4);   aH[cur ^ 1][3] = __ldcg(Hhi + o + 2052);
                aL[cur ^ 1][0] = __ldcg(Hlo + o);       aL[cur ^ 1][1] = __ldcg(Hlo + o + 2048);
                aL[cur ^ 1][2] = __ldcg(Hlo + o + 4);   aL[cur ^ 1][3] = __ldcg(Hlo + o + 2052);
            }
            const int kb   = kt * 16 + (lane & 3) * 2;
            const int nrow = lane >> 2;
#pragma unroll
            for (int g = 0; g < 4; ++g) {
                uint32_t bh[2], bl[2];
                const __nv_bfloat16* ph = &sW[(g * 8 + nrow) * KPAD + kb];
                const __nv_bfloat16* pl = &sW[(32 + g * 8 + nrow) * KPAD + kb];
                bh[0] = *(const uint32_t*)ph;  bh[1] = *(const uint32_t*)(ph + 8);
                bl[0] = *(const uint32_t*)pl;  bl[1] = *(const uint32_t*)(pl + 8);
                mma_bf16(acc[g], aH[cur], bh);
                mma_bf16(acc[g], aL[cur], bh);
                mma_bf16(acc[g], aH[cur], bl);
            }
        }

#pragma unroll
        for (int ri = 0; ri < 2; ++ri) {
            const int m   = r0 + ri * 8;
            const int b   = b0 + ri * 8;
            const int len = len_[ri];
            const int tpos = dir ? ((t < len) ? (len - 1 - t) : t) : t;
            const int rowx = (seq * Bq + b) * Tq + tpos;
            const float* xwr = &d_xW[dir][rowx][0];
            const float2 gi2 = *(const float2*)&xwr[c0j];
            const float2 gf2 = *(const float2*)&xwr[Hq + c0j];
            const float2 gg2 = *(const float2*)&xwr[2 * Hq + c0j];
            const float2 go2 = *(const float2*)&xwr[3 * Hq + c0j];
#pragma unroll
            for (int ci = 0; ci < 2; ++ci) {
                const int ai = ri * 2 + ci;
                float gi = acc[0][ai] + (ci ? gi2.y : gi2.x);
                float gf = acc[1][ai] + (ci ? gf2.y : gf2.x);
                float gg = acc[2][ai] + (ci ? gg2.y : gg2.x);
                float go = acc[3][ai] + (ci ? go2.y : go2.x);
                float si = 1.f / (1.f + expf(-gi));
                float sf = 1.f / (1.f + expf(-gf));
                float so = 1.f / (1.f + expf(-go));
                float c  = sf * creg[ai] + si * tanhf(gg);
                float h  = so * tanhf(c);
                creg[ai] = c;
                d_Hout[rowx][dir * Hq + c0j + ci] = h;
                __nv_bfloat16 hh = __float2bfloat16(h);
                __nv_bfloat16 hl = __float2bfloat16(h - __bfloat162float(hh));
                d_h16[p ^ 1][0][dir][m][c0j + ci] = hh;
                d_h16[p ^ 1][1][dir][m][c0j + ci] = hl;
                d_Ho16[0][rowx][dir * Hq + c0j + ci] = hh;   // for attn_mma
                d_Ho16[1][rowx][dir * Hq + c0j + ci] = hl;
            }
        }

        __syncthreads();
        if (tid == 0) {
            __threadfence();
            unsigned arrived = atomicAdd(&g_cnt, 1);
            if (arrived == NCTA - 1) {
                g_cnt = 0;
                __threadfence();
                atomicExch(&g_epoch, myep + 1);
            } else {
                while (*(volatile unsigned*)&g_epoch <= myep) { }
            }
            __threadfence();
        }
        myep++;
        __syncthreads();
    }
}

// ---------------- attention projection via tensor cores ----------------------
// P[16384,256] = Hout[16384,1024] @ S1W^T. CTA 64x256, grid (1, 256).
__global__ __launch_bounds__(256)
void attn_mma() {
    const int lane = threadIdx.x & 31;
    const int warp = threadIdx.x >> 5;
    const int wm = warp & 1, wn = warp >> 1;
    const int m0 = blockIdx.y * 64 + wm * 32;
    const int n0 = wn * 64;
    const int RS = D2H / 2;                // 512 u32 per row
    const int kc = lane & 3;
    const int rr = lane >> 2;

    const uint32_t* Xhi = (const uint32_t*)&d_Ho16[0][0][0];
    const uint32_t* Xlo = (const uint32_t*)&d_Ho16[1][0][0];
    const uint32_t* Whi = (const uint32_t*)&d_S1W16[0][0][0];
    const uint32_t* Wlo = (const uint32_t*)&d_S1W16[1][0][0];

    float acc[2][8][4] = {};

    for (int kt = 0; kt < D2H / 16; ++kt) {
        const int k0 = kt * 8;
        uint32_t aH[2][4], aL[2][4];
#pragma unroll
        for (int mt = 0; mt < 2; ++mt) {
            int base = (m0 + mt * 16 + rr) * RS + k0 + kc;
            aH[mt][0] = Xhi[base];          aH[mt][1] = Xhi[base + 8 * RS];
            aH[mt][2] = Xhi[base + 4];      aH[mt][3] = Xhi[base + 8 * RS + 4];
            aL[mt][0] = Xlo[base];          aL[mt][1] = Xlo[base + 8 * RS];
            aL[mt][2] = Xlo[base + 4];      aL[mt][3] = Xlo[base + 8 * RS + 4];
        }
#pragma unroll
        for (int nt = 0; nt < 8; ++nt) {
            int bb = (n0 + nt * 8 + rr) * RS + k0 + kc;
            uint32_t bh[2] = { Whi[bb], Whi[bb + 4] };
            uint32_t bl[2] = { Wlo[bb], Wlo[bb + 4] };
#pragma unroll
            for (int mt = 0; mt < 2; ++mt) {
                mma_bf16(acc[mt][nt], aH[mt], bh);
                mma_bf16(acc[mt][nt], aL[mt], bh);
                mma_bf16(acc[mt][nt], aH[mt], bl);
            }
        }
    }
#pragma unroll
    for (int mt = 0; mt < 2; ++mt)
#pragma unroll
        for (int nt = 0; nt < 8; ++nt) {
            int r  = m0 + mt * 16 + rr;
            int cc = n0 + nt * 8 + (lane & 3) * 2;
#pragma unroll
            for (int i = 0; i < 4; ++i)
                d_P[r + (i >> 1) * 8][cc + (i & 1)] = acc[mt][nt][i];
        }
}

// ---------------- masked softmax attention pooling ---------------------------
__global__ __launch_bounds__(128)
void attn_pool(const int* __restrict__ s1_len, const int* __restrict__ s2_len,
               const float* __restrict__ S2W) {
    __shared__ float sS2[Cq];
    __shared__ float ssc[Tq];
    __shared__ float red[Tq];
    int sb = blockIdx.x;
    int seq = sb >> 6, b = sb & 63;
    int t = threadIdx.x;
    for (int c = t; c < Cq; c += Tq) sS2[c] = S2W[c];
    __syncthreads();

    long row = (long)sb * Tq + t;
    float s = 0.f;
    for (int c = 0; c < Cq; ++c) s += tanhf(d_P[row][c]) * sS2[c];
    int len = (seq ? s2_len : s1_len)[b];
    ssc[t] = (t < len) ? s : -1e9f;
    __syncthreads();

    red[t] = ssc[t]; __syncthreads();
    for (int o = 64; o > 0; o >>= 1) { if (t < o) red[t] = fmaxf(red[t], red[t + o]); __syncthreads(); }
    float mx = red[0]; __syncthreads();
    float ex = expf(ssc[t] - mx);
    red[t] = ex; __syncthreads();
    for (int o = 64; o > 0; o >>= 1) { if (t < o) red[t] += red[t + o]; __syncthreads(); }
    float inv = 1.f / red[0];
    __syncthreads();
    ssc[t] = ex * inv;
    __syncthreads();

    long rowbase = (long)sb * Tq;
    for (int d = t; d < D2H; d += Tq) {
        float acc = 0.f;
        for (int tt = 0; tt < Tq; ++tt) acc += ssc[tt] * d_Hout[rowbase + tt][d];
        d_r[seq][b][d] = acc;
    }
}

// ---------------- final MLP head + sigmoid ----------------------------------
__global__ __launch_bounds__(512)
void final_mlp(const float* __restrict__ mlpW, const float* __restrict__ mlpb,
               const float* __restrict__ outW, const float* __restrict__ outb,
               float* __restrict__ out) {
    __shared__ float merged[4 * Hq];
    __shared__ float smlp[Mq];
    __shared__ float red[16];
    int b = blockIdx.x;
    int tid = threadIdx.x;

    for (int d = tid; d < 2 * D2H; d += Mq) {
        float v;
        if (d < D2H) v = d_r[0][b][d] + d_r[1][b][d];
        else { float df = d_r[0][b][d - D2H] - d_r[1][b][d - D2H]; v = df * df; }
        merged[d] = v;
    }
    __syncthreads();

    int warp = tid >> 5, lane = tid & 31;
    for (int m = warp * 32; m < warp * 32 + 32; ++m) {
        float p = 0.f;
        for (int d = lane; d < 4 * Hq; d += 32) p += merged[d] * mlpW[(long)m * 4 * Hq + d];
        for (int o = 16; o > 0; o >>= 1) p += __shfl_down_sync(0xffffffff, p, o);
        if (lane == 0) smlp[m] = p + mlpb[m];
    }
    __syncthreads();

    float p = smlp[tid] * outW[tid];
    for (int o = 16; o > 0; o >>= 1) p += __shfl_down_sync(0xffffffff, p, o);
    if (lane == 0) red[warp] = p;
    __syncthreads();
    if (tid == 0) {
        float l = outb[0];
        for (int w = 0; w < 16; ++w) l += red[w];
        out[b] = 1.f / (1.f + expf(-l));
    }
}

// ---------------- launch ------------------------------------------------------
extern "C" void kernel_launch(void* const* d_in, const int* in_sizes, int n_in,
                              void* d_out, int out_size) {
    const int*   s1     = (const int*)d_in[0];
    const int*   s2     = (const int*)d_in[1];
    const int*   s1_len = (const int*)d_in[2];
    const int*   s2_len = (const int*)d_in[3];
    const float* s1_h0  = (const float*)d_in[4];
    const float* s1_c0  = (const float*)d_in[5];
    const float* s2_h0  = (const float*)d_in[6];
    const float* s2_c0  = (const float*)d_in[7];
    const float* emb    = (const float*)d_in[8];
    const float* Wih_f  = (const float*)d_in[9];
    const float* Whh_f  = (const float*)d_in[10];
    const float* b_f    = (const float*)d_in[11];
    const float* Wih_b  = (const float*)d_in[12];
    const float* Whh_b  = (const float*)d_in[13];
    const float* b_b    = (const float*)d_in[14];
    const float* S1W    = (const float*)d_in[15];
    const float* S2W    = (const float*)d_in[16];
    const float* mlpW   = (const float*)d_in[17];
    const float* mlpb   = (const float*)d_in[18];
    const float* outW   = (const float*)d_in[19];
    const float* outb   = (const float*)d_in[20];
    float* out = (float*)d_out;

    const int smem_lstm = 2 * 4 * 8 * KPAD * (int)sizeof(__nv_bfloat16);  // 66560
    cudaFuncSetAttribute(lstm_persist, cudaFuncAttributeMaxDynamicSharedMemorySize, smem_lstm);

    init_state<<<(2 * 128 * Hq + 255) / 256, 256>>>(s1_h0, s2_h0);
    prep_weights<<<(2 * G4H * Hq + 255) / 256, 256>>>(Whh_f, Whh_b);
    gather_convert<<<(NROWS * KE + 255) / 256, 256>>>(s1, s2, emb);
    convert_wih<<<(2 * G4H * KE + 255) / 256, 256>>>(Wih_f, Wih_b, b_f, b_b);
    convert_s1w<<<(Cq * D2H + 255) / 256, 256>>>(S1W);

    xw_mma<<<dim3(16, 256), 256>>>();                  // both dirs fused

    lstm_persist<<<NCTA, 256, smem_lstm>>>(s1_len, s2_len, s1_c0, s2_c0);

    attn_mma<<<dim3(1, 256), 256>>>();
    attn_pool<<<128, 128>>>(s1_len, s2_len, S2W);
    final_mlp<<<Bq, 512>>>(mlpW, mlpb, outW, outb, out);
}

// round 7
// speedup vs baseline: 2.0347x; 1.1356x over previous
#include <cuda_runtime.h>
#include <cuda_bf16.h>
#include <stdint.h>
#include <math.h>

// Problem constants
#define Bq   64
#define Tq   128
#define Eq   300
#define Hq   512
#define Cq   256
#define Mq   512
#define RPS  (Bq*Tq)      // rows per sequence: 8192
#define NROWS (2*RPS)     // 16384
#define G4H  (4*Hq)       // 2048
#define D2H  (2*Hq)       // 1024
#define NCTA 128          // persistent LSTM grid (64 per direction)
#define KE   304          // Eq padded to multiple of 16

// -------- scratch (static device globals; no allocation anywhere) -----------
__device__ float d_xW[2][NROWS][G4H];    // [dir][(seq*B+b)*T+t][4H]
__device__ float d_Hout[NROWS][D2H];     // bi-LSTM outputs (fp32, for attn_pool)
__device__ float d_P[NROWS][Cq];         // attention pre-activations
__device__ float d_r[2][Bq][D2H];        // pooled representations
__device__ __nv_bfloat16 d_Wb16[2][2][G4H][Hq];      // [dir][hi/lo][n][k]  Whh
__device__ __nv_bfloat16 d_h16[2][2][2][128][Hq];    // [parity][hi/lo][dir][m][k]
__device__ __nv_bfloat16 d_x16[2][NROWS][KE];        // [hi/lo] gathered embeddings
__device__ __nv_bfloat16 d_W16[2][2*G4H][KE];        // [hi/lo][dir*2048+n][k] Wih
__device__ float d_biasC[2*G4H];                     // combined Wih bias
__device__ __nv_bfloat16 d_Ho16[2][NROWS][D2H];      // [hi/lo] bf16 Hout
__device__ __nv_bfloat16 d_S1W16[2][Cq][D2H];        // [hi/lo] S1W
__device__ unsigned g_cnt2[2];
__device__ unsigned g_epoch2[2];

// ---- fast activations (MUFU.EX2-based; rel err ~1e-7, margin is 1e-3) ------
__device__ __forceinline__ float fsigmoid(float x) {
    return __fdividef(1.f, 1.f + __expf(-x));
}
__device__ __forceinline__ float ftanh(float x) {
    return 1.f - __fdividef(2.f, 1.f + __expf(2.f * x));
}

// ---------------- init: reset barriers, seed h16 from h0 --------------------
__global__ void init_state(const float* s1_h0, const float* s2_h0) {
    int idx = blockIdx.x * blockDim.x + threadIdx.x;
    if (idx < 2) { g_cnt2[idx] = 0; g_epoch2[idx] = 0; }
    if (idx >= 2 * 128 * Hq) return;
    int j   = idx % Hq;
    int m   = (idx / Hq) % 128;
    int dir = idx / (Hq * 128);
    int seq = m >> 6, b = m & 63;
    float h = (seq ? s2_h0 : s1_h0)[(dir * Bq + b) * Hq + j];
    __nv_bfloat16 hh = __float2bfloat16(h);
    __nv_bfloat16 hl = __float2bfloat16(h - __bfloat162float(hh));
    d_h16[0][0][dir][m][j] = hh;
    d_h16[0][1][dir][m][j] = hl;
}

// ---------------- split Whh into bf16 hi/lo ----------------------------------
__global__ void prep_weights(const float* __restrict__ Whh_f,
                             const float* __restrict__ Whh_b) {
    int idx = blockIdx.x * blockDim.x + threadIdx.x;
    if (idx >= 2 * G4H * Hq) return;
    int dir = idx / (G4H * Hq);
    int r   = idx % (G4H * Hq);
    float w = (dir ? Whh_b : Whh_f)[r];
    __nv_bfloat16 hi = __float2bfloat16(w);
    __nv_bfloat16 lo = __float2bfloat16(w - __bfloat162float(hi));
    int n = r / Hq, k = r % Hq;
    d_Wb16[dir][0][n][k] = hi;
    d_Wb16[dir][1][n][k] = lo;
}

// ---------------- gather tokens + convert emb rows to bf16 hi/lo -------------
__global__ void gather_convert(const int* __restrict__ s1, const int* __restrict__ s2,
                               const float* __restrict__ emb) {
    int idx = blockIdx.x * blockDim.x + threadIdx.x;
    if (idx >= NROWS * KE) return;
    int m = idx / KE, k = idx % KE;
    int tok = (m < RPS) ? s1[m] : s2[m - RPS];
    float v = (k < Eq) ? emb[(long)tok * Eq + k] : 0.f;
    __nv_bfloat16 hi = __float2bfloat16(v);
    d_x16[0][m][k] = hi;
    d_x16[1][m][k] = __float2bfloat16(v - __bfloat162float(hi));
}

// ---------------- convert Wih (both dirs) to bf16 hi/lo + combined bias ------
__global__ void convert_wih(const float* __restrict__ Wih_f, const float* __restrict__ Wih_b,
                            const float* __restrict__ b_f, const float* __restrict__ b_b) {
    int idx = blockIdx.x * blockDim.x + threadIdx.x;
    if (idx >= 2 * G4H * KE) return;
    int n = idx / KE, k = idx % KE;
    int dir = n >> 11, nn = n & 2047;
    const float* W = dir ? Wih_b : Wih_f;
    float v = (k < Eq) ? W[(long)nn * Eq + k] : 0.f;
    __nv_bfloat16 hi = __float2bfloat16(v);
    d_W16[0][n][k] = hi;
    d_W16[1][n][k] = __float2bfloat16(v - __bfloat162float(hi));
    if (k == 0) d_biasC[n] = (dir ? b_b : b_f)[nn];
}

// ---------------- convert S1W to bf16 hi/lo -----------------------------------
__global__ void convert_s1w(const float* __restrict__ S1W) {
    int idx = blockIdx.x * blockDim.x + threadIdx.x;
    if (idx >= Cq * D2H) return;
    float v = S1W[idx];
    int c = idx / D2H, k = idx % D2H;
    __nv_bfloat16 hi = __float2bfloat16(v);
    d_S1W16[0][c][k] = hi;
    d_S1W16[1][c][k] = __float2bfloat16(v - __bfloat162float(hi));
}

// ---------------- mma.sync bf16 helper ---------------------------------------
__device__ __forceinline__ void mma_bf16(float* d, const uint32_t* a, const uint32_t* b) {
    asm volatile(
        "mma.sync.aligned.m16n8k16.row.col.f32.bf16.bf16.f32 "
        "{%0,%1,%2,%3}, {%4,%5,%6,%7}, {%8,%9}, {%0,%1,%2,%3};\n"
        : "+f"(d[0]), "+f"(d[1]), "+f"(d[2]), "+f"(d[3])
        : "r"(a[0]), "r"(a[1]), "r"(a[2]), "r"(a[3]),
          "r"(b[0]), "r"(b[1]));
}

// ---------------- xW via tensor cores: [16384,304] @ [304,4096] --------------
__global__ __launch_bounds__(256)
void xw_mma() {
    const int lane = threadIdx.x & 31;
    const int warp = threadIdx.x >> 5;
    const int wm = warp & 1, wn = warp >> 1;
    const int m0 = blockIdx.y * 64 + wm * 32;
    const int n0 = blockIdx.x * 256 + wn * 64;
    const int RS = KE / 2;                 // u32 row stride (152)
    const int kc = lane & 3;
    const int rr = lane >> 2;

    const uint32_t* Xhi = (const uint32_t*)&d_x16[0][0][0];
    const uint32_t* Xlo = (const uint32_t*)&d_x16[1][0][0];
    const uint32_t* Whi = (const uint32_t*)&d_W16[0][0][0];
    const uint32_t* Wlo = (const uint32_t*)&d_W16[1][0][0];

    float acc[2][8][4] = {};

    for (int kt = 0; kt < KE / 16; ++kt) {
        const int k0 = kt * 8;
        uint32_t aH[2][4], aL[2][4];
#pragma unroll
        for (int mt = 0; mt < 2; ++mt) {
            int base = (m0 + mt * 16 + rr) * RS + k0 + kc;
            aH[mt][0] = Xhi[base];          aH[mt][1] = Xhi[base + 8 * RS];
            aH[mt][2] = Xhi[base + 4];      aH[mt][3] = Xhi[base + 8 * RS + 4];
            aL[mt][0] = Xlo[base];          aL[mt][1] = Xlo[base + 8 * RS];
            aL[mt][2] = Xlo[base + 4];      aL[mt][3] = Xlo[base + 8 * RS + 4];
        }
#pragma unroll
        for (int nt = 0; nt < 8; ++nt) {
            int bb = (n0 + nt * 8 + rr) * RS + k0 + kc;
            uint32_t bh[2] = { Whi[bb], Whi[bb + 4] };
            uint32_t bl[2] = { Wlo[bb], Wlo[bb + 4] };
#pragma unroll
            for (int mt = 0; mt < 2; ++mt) {
                mma_bf16(acc[mt][nt], aH[mt], bh);
                mma_bf16(acc[mt][nt], aL[mt], bh);
                mma_bf16(acc[mt][nt], aH[mt], bl);
            }
        }
    }
#pragma unroll
    for (int mt = 0; mt < 2; ++mt)
#pragma unroll
        for (int nt = 0; nt < 8; ++nt) {
            int r  = m0 + mt * 16 + rr;
            int cc = n0 + nt * 8 + (lane & 3) * 2;
#pragma unroll
            for (int i = 0; i < 4; ++i) {
                int m = r + (i >> 1) * 8;
                int n = cc + (i & 1);
                int dir = n >> 11, nn = n & 2047;
                d_xW[dir][m][nn] = acc[mt][nt][i] + d_biasC[n];
            }
        }
}

// ---------------- persistent LSTM: all 128 steps, tensor cores ---------------
// 128 CTAs (64/dir), per-dir grid barrier. Whh in fragment-major smem (LDS.64).
// 3-deep h prefetch ring; xW gate values prefetched at step start.
__global__ __launch_bounds__(256)
void lstm_persist(const int* __restrict__ s1_len, const int* __restrict__ s2_len,
                  const float* __restrict__ s1_c0, const float* __restrict__ s2_c0) {
    extern __shared__ uint32_t sWf[];   // 64KB: [s][g][kt][lane*2(+1)] fragment-major
    const int tid  = threadIdx.x;
    const int lane = tid & 31;
    const int warp = tid >> 5;
    const int dir  = blockIdx.x & 1;
    const int j0   = (blockIdx.x >> 1) * 8;

    // ---- fragment-major weight fill (once) ----
    const uint32_t* Wsrc = (const uint32_t*)&d_Wb16[dir][0][0][0];  // [s][n][k/2]
    for (int i = tid; i < 8192; i += 256) {
        int l  = i & 31;
        int kt = (i >> 5) & 31;
        int g  = (i >> 10) & 3;
        int s  = i >> 12;
        int n  = l >> 2;
        int k0 = kt * 16 + (l & 3) * 2;
        long srow = (long)s * (G4H * (Hq / 2)) + (long)(g * Hq + j0 + n) * (Hq / 2);
        sWf[2 * i]     = Wsrc[srow + (k0 >> 1)];
        sWf[2 * i + 1] = Wsrc[srow + ((k0 + 8) >> 1)];
    }

    // ---- per-thread ownership ----
    const int m0  = warp * 16;
    const int seq = m0 >> 6;
    const int r0  = m0 + (lane >> 2);
    const int c0j = j0 + (lane & 3) * 2;
    const int*   lens = seq ? s2_len : s1_len;
    const float* c0p  = seq ? s2_c0  : s1_c0;
    const int b0 = r0 & 63;
    const int len_[2] = { lens[b0], lens[b0 + 8] };

    float creg[4];
#pragma unroll
    for (int ri = 0; ri < 2; ++ri)
#pragma unroll
        for (int ci = 0; ci < 2; ++ci)
            creg[ri * 2 + ci] = c0p[(dir * Bq + b0 + 8 * ri) * Hq + c0j + ci];

    __syncthreads();

    const int oA = (r0 * Hq + (lane & 3) * 2) >> 1;   // u32 index into h slab
    unsigned myep = 0;

    for (int t = 0; t < Tq; ++t) {
        const int p = t & 1;
        const uint32_t* Hhi = (const uint32_t*)&d_h16[p][0][dir][0][0];
        const uint32_t* Hlo = (const uint32_t*)&d_h16[p][1][dir][0][0];

        // ---- prefetch xW gate values for this step (DRAM latency overlap) ----
        int rowx_[2];
        float2 pgi[2], pgf[2], pgg[2], pgo[2];
#pragma unroll
        for (int ri = 0; ri < 2; ++ri) {
            int b = b0 + 8 * ri;
            int len = len_[ri];
            int tpos = dir ? ((t < len) ? (len - 1 - t) : t) : t;
            rowx_[ri] = (seq * Bq + b) * Tq + tpos;
            const float* xwr = &d_xW[dir][rowx_[ri]][0];
            pgi[ri] = __ldcs((const float2*)&xwr[c0j]);
            pgf[ri] = __ldcs((const float2*)&xwr[Hq + c0j]);
            pgg[ri] = __ldcs((const float2*)&xwr[2 * Hq + c0j]);
            pgo[ri] = __ldcs((const float2*)&xwr[3 * Hq + c0j]);
        }

        float acc[4][4] = {};
        uint32_t aH[3][4], aL[3][4];

#define LOADA(buf, ktv) { int o = oA + (ktv) * 8;                                              \
        aH[buf][0] = __ldcg(Hhi + o);      aH[buf][1] = __ldcg(Hhi + o + 2048);                \
        aH[buf][2] = __ldcg(Hhi + o + 4);  aH[buf][3] = __ldcg(Hhi + o + 2052);                \
        aL[buf][0] = __ldcg(Hlo + o);      aL[buf][1] = __ldcg(Hlo + o + 2048);                \
        aL[buf][2] = __ldcg(Hlo + o + 4);  aL[buf][3] = __ldcg(Hlo + o + 2052); }

        LOADA(0, 0);
        LOADA(1, 1);

#pragma unroll
        for (int kt = 0; kt < 32; ++kt) {
            const int cur = kt % 3;
            if (kt < 30) { LOADA((kt + 2) % 3, kt + 2); }
#pragma unroll
            for (int g = 0; g < 4; ++g) {
                const uint2 bh2 = *(const uint2*)&sWf[(g * 32 + kt) * 64 + lane * 2];
                const uint2 bl2 = *(const uint2*)&sWf[((4 + g) * 32 + kt) * 64 + lane * 2];
                uint32_t bh[2] = { bh2.x, bh2.y };
                uint32_t bl[2] = { bl2.x, bl2.y };
                mma_bf16(acc[g], aH[cur], bh);
                mma_bf16(acc[g], aL[cur], bh);
                mma_bf16(acc[g], aH[cur], bl);
            }
        }
#undef LOADA

        // ---- epilogue: gates, cell/h update, publish h ----
#pragma unroll
        for (int ri = 0; ri < 2; ++ri) {
            const int m    = r0 + ri * 8;
            const int rowx = rowx_[ri];
#pragma unroll
            for (int ci = 0; ci < 2; ++ci) {
                const int ai = ri * 2 + ci;
                float gi = acc[0][ai] + (ci ? pgi[ri].y : pgi[ri].x);
                float gf = acc[1][ai] + (ci ? pgf[ri].y : pgf[ri].x);
                float gg = acc[2][ai] + (ci ? pgg[ri].y : pgg[ri].x);
                float go = acc[3][ai] + (ci ? pgo[ri].y : pgo[ri].x);
                float c  = fsigmoid(gf) * creg[ai] + fsigmoid(gi) * ftanh(gg);
                float h  = fsigmoid(go) * ftanh(c);
                creg[ai] = c;
                d_Hout[rowx][dir * Hq + c0j + ci] = h;
                __nv_bfloat16 hh = __float2bfloat16(h);
                __nv_bfloat16 hl = __float2bfloat16(h - __bfloat162float(hh));
                d_h16[p ^ 1][0][dir][m][c0j + ci] = hh;
                d_h16[p ^ 1][1][dir][m][c0j + ci] = hl;
                d_Ho16[0][rowx][dir * Hq + c0j + ci] = hh;
                d_Ho16[1][rowx][dir * Hq + c0j + ci] = hl;
            }
        }

        // ---- per-direction grid barrier ----
        __syncthreads();
        if (tid == 0) {
            __threadfence();
            unsigned arrived = atomicAdd(&g_cnt2[dir], 1);
            if (arrived == NCTA / 2 - 1) {
                g_cnt2[dir] = 0;
                __threadfence();
                atomicExch(&g_epoch2[dir], myep + 1);
            } else {
                while (*(volatile unsigned*)&g_epoch2[dir] <= myep) { }
            }
            __threadfence();
        }
        myep++;
        __syncthreads();
    }
}

// ---------------- attention projection via tensor cores ----------------------
__global__ __launch_bounds__(256)
void attn_mma() {
    const int lane = threadIdx.x & 31;
    const int warp = threadIdx.x >> 5;
    const int wm = warp & 1, wn = warp >> 1;
    const int m0 = blockIdx.y * 64 + wm * 32;
    const int n0 = wn * 64;
    const int RS = D2H / 2;
    const int kc = lane & 3;
    const int rr = lane >> 2;

    const uint32_t* Xhi = (const uint32_t*)&d_Ho16[0][0][0];
    const uint32_t* Xlo = (const uint32_t*)&d_Ho16[1][0][0];
    const uint32_t* Whi = (const uint32_t*)&d_S1W16[0][0][0];
    const uint32_t* Wlo = (const uint32_t*)&d_S1W16[1][0][0];

    float acc[2][8][4] = {};

    for (int kt = 0; kt < D2H / 16; ++kt) {
        const int k0 = kt * 8;
        uint32_t aH[2][4], aL[2][4];
#pragma unroll
        for (int mt = 0; mt < 2; ++mt) {
            int base = (m0 + mt * 16 + rr) * RS + k0 + kc;
            aH[mt][0] = Xhi[base];          aH[mt][1] = Xhi[base + 8 * RS];
            aH[mt][2] = Xhi[base + 4];      aH[mt][3] = Xhi[base + 8 * RS + 4];
            aL[mt][0] = Xlo[base];          aL[mt][1] = Xlo[base + 8 * RS];
            aL[mt][2] = Xlo[base + 4];      aL[mt][3] = Xlo[base + 8 * RS + 4];
        }
#pragma unroll
        for (int nt = 0; nt < 8; ++nt) {
            int bb = (n0 + nt * 8 + rr) * RS + k0 + kc;
            uint32_t bh[2] = { Whi[bb], Whi[bb + 4] };
            uint32_t bl[2] = { Wlo[bb], Wlo[bb + 4] };
#pragma unroll
            for (int mt = 0; mt < 2; ++mt) {
                mma_bf16(acc[mt][nt], aH[mt], bh);
                mma_bf16(acc[mt][nt], aL[mt], bh);
                mma_bf16(acc[mt][nt], aH[mt], bl);
            }
        }
    }
#pragma unroll
    for (int mt = 0; mt < 2; ++mt)
#pragma unroll
        for (int nt = 0; nt < 8; ++nt) {
            int r  = m0 + mt * 16 + rr;
            int cc = n0 + nt * 8 + (lane & 3) * 2;
#pragma unroll
            for (int i = 0; i < 4; ++i)
                d_P[r + (i >> 1) * 8][cc + (i & 1)] = acc[mt][nt][i];
        }
}

// ---------------- masked softmax attention pooling ---------------------------
__global__ __launch_bounds__(128)
void attn_pool(const int* __restrict__ s1_len, const int* __restrict__ s2_len,
               const float* __restrict__ S2W) {
    __shared__ float sS2[Cq];
    __shared__ float ssc[Tq];
    __shared__ float red[Tq];
    int sb = blockIdx.x;
    int seq = sb >> 6, b = sb & 63;
    int t = threadIdx.x;
    for (int c = t; c < Cq; c += Tq) sS2[c] = S2W[c];
    __syncthreads();

    long row = (long)sb * Tq + t;
    float s = 0.f;
    for (int c = 0; c < Cq; ++c) s += ftanh(d_P[row][c]) * sS2[c];
    int len = (seq ? s2_len : s1_len)[b];
    ssc[t] = (t < len) ? s : -1e9f;
    __syncthreads();

    red[t] = ssc[t]; __syncthreads();
    for (int o = 64; o > 0; o >>= 1) { if (t < o) red[t] = fmaxf(red[t], red[t + o]); __syncthreads(); }
    float mx = red[0]; __syncthreads();
    float ex = expf(ssc[t] - mx);
    red[t] = ex; __syncthreads();
    for (int o = 64; o > 0; o >>= 1) { if (t < o) red[t] += red[t + o]; __syncthreads(); }
    float inv = 1.f / red[0];
    __syncthreads();
    ssc[t] = ex * inv;
    __syncthreads();

    long rowbase = (long)sb * Tq;
    for (int d = t; d < D2H; d += Tq) {
        float acc = 0.f;
        for (int tt = 0; tt < Tq; ++tt) acc += ssc[tt] * d_Hout[rowbase + tt][d];
        d_r[seq][b][d] = acc;
    }
}

// ---------------- final MLP head + sigmoid ----------------------------------
__global__ __launch_bounds__(512)
void final_mlp(const float* __restrict__ mlpW, const float* __restrict__ mlpb,
               const float* __restrict__ outW, const float* __restrict__ outb,
               float* __restrict__ out) {
    __shared__ float merged[4 * Hq];
    __shared__ float smlp[Mq];
    __shared__ float red[16];
    int b = blockIdx.x;
    int tid = threadIdx.x;

    for (int d = tid; d < 2 * D2H; d += Mq) {
        float v;
        if (d < D2H) v = d_r[0][b][d] + d_r[1][b][d];
        else { float df = d_r[0][b][d - D2H] - d_r[1][b][d - D2H]; v = df * df; }
        merged[d] = v;
    }
    __syncthreads();

    int warp = tid >> 5, lane = tid & 31;
    for (int m = warp * 32; m < warp * 32 + 32; ++m) {
        float p = 0.f;
        for (int d = lane; d < 4 * Hq; d += 32) p += merged[d] * mlpW[(long)m * 4 * Hq + d];
        for (int o = 16; o > 0; o >>= 1) p += __shfl_down_sync(0xffffffff, p, o);
        if (lane == 0) smlp[m] = p + mlpb[m];
    }
    __syncthreads();

    float p = smlp[tid] * outW[tid];
    for (int o = 16; o > 0; o >>= 1) p += __shfl_down_sync(0xffffffff, p, o);
    if (lane == 0) red[warp] = p;
    __syncthreads();
    if (tid == 0) {
        float l = outb[0];
        for (int w = 0; w < 16; ++w) l += red[w];
        out[b] = 1.f / (1.f + expf(-l));
    }
}

// ---------------- launch ------------------------------------------------------
extern "C" void kernel_launch(void* const* d_in, const int* in_sizes, int n_in,
                              void* d_out, int out_size) {
    const int*   s1     = (const int*)d_in[0];
    const int*   s2     = (const int*)d_in[1];
    const int*   s1_len = (const int*)d_in[2];
    const int*   s2_len = (const int*)d_in[3];
    const float* s1_h0  = (const float*)d_in[4];
    const float* s1_c0  = (const float*)d_in[5];
    const float* s2_h0  = (const float*)d_in[6];
    const float* s2_c0  = (const float*)d_in[7];
    const float* emb    = (const float*)d_in[8];
    const float* Wih_f  = (const float*)d_in[9];
    const float* Whh_f  = (const float*)d_in[10];
    const float* b_f    = (const float*)d_in[11];
    const float* Wih_b  = (const float*)d_in[12];
    const float* Whh_b  = (const float*)d_in[13];
    const float* b_b    = (const float*)d_in[14];
    const float* S1W    = (const float*)d_in[15];
    const float* S2W    = (const float*)d_in[16];
    const float* mlpW   = (const float*)d_in[17];
    const float* mlpb   = (const float*)d_in[18];
    const float* outW   = (const float*)d_in[19];
    const float* outb   = (const float*)d_in[20];
    float* out = (float*)d_out;

    const int smem_lstm = 16384 * (int)sizeof(uint32_t);   // 64KB
    cudaFuncSetAttribute(lstm_persist, cudaFuncAttributeMaxDynamicSharedMemorySize, smem_lstm);

    init_state<<<(2 * 128 * Hq + 255) / 256, 256>>>(s1_h0, s2_h0);
    prep_weights<<<(2 * G4H * Hq + 255) / 256, 256>>>(Whh_f, Whh_b);
    gather_convert<<<(NROWS * KE + 255) / 256, 256>>>(s1, s2, emb);
    convert_wih<<<(2 * G4H * KE + 255) / 256, 256>>>(Wih_f, Wih_b, b_f, b_b);
    convert_s1w<<<(Cq * D2H + 255) / 256, 256>>>(S1W);

    xw_mma<<<dim3(16, 256), 256>>>();                  // both dirs fused

    lstm_persist<<<NCTA, 256, smem_lstm>>>(s1_len, s2_len, s1_c0, s2_c0);

    attn_mma<<<dim3(1, 256), 256>>>();
    attn_pool<<<128, 128>>>(s1_len, s2_len, S2W);
    final_mlp<<<Bq, 512>>>(mlpW, mlpb, outW, outb, out);
}

// round 8
// speedup vs baseline: 2.7110x; 1.3324x over previous
#include <cuda_runtime.h>
#include <cuda_bf16.h>
#include <stdint.h>
#include <math.h>

// Problem constants
#define Bq   64
#define Tq   128
#define Eq   300
#define Hq   512
#define Cq   256
#define Mq   512
#define RPS  (Bq*Tq)      // rows per sequence: 8192
#define NROWS (2*RPS)     // 16384
#define G4H  (4*Hq)       // 2048
#define D2H  (2*Hq)       // 1024
#define NCTA 128          // persistent LSTM grid (64 per direction)
#define KE   304          // Eq padded to multiple of 16

// -------- scratch (static device globals; no allocation anywhere) -----------
__device__ float d_xW[2][NROWS][G4H];    // [dir][(seq*B+b)*T+t][4H]
__device__ float d_P[NROWS][Cq];         // attention pre-activations
__device__ float d_r[2][Bq][D2H];        // pooled representations
__device__ __nv_bfloat16 d_Wb16[2][2][G4H][Hq];      // [dir][hi/lo][n][k]  Whh
// h state in mma-A-fragment-major layout:
// [parity][split][dir][mblock(8)][ktile(32)][lane(32)][slot(4)]  (u32 = 2 bf16)
__device__ uint32_t d_h16f[2][2][2][8][32][32][4];
__device__ __nv_bfloat16 d_x16[2][NROWS][KE];        // [hi/lo] gathered embeddings
__device__ __nv_bfloat16 d_W16[2][2*G4H][KE];        // [hi/lo][dir*2048+n][k] Wih
__device__ float d_biasC[2*G4H];                     // combined Wih bias
__device__ __nv_bfloat16 d_Ho16[2][NROWS][D2H];      // [hi/lo] bf16 Hout
__device__ __nv_bfloat16 d_S1W16[2][Cq][D2H];        // [hi/lo] S1W
__device__ unsigned g_cnt2[2];
__device__ unsigned g_epoch2[2];

// ---- fast activations (MUFU.EX2-based) --------------------------------------
__device__ __forceinline__ float fsigmoid(float x) {
    return __fdividef(1.f, 1.f + __expf(-x));
}
__device__ __forceinline__ float ftanh(float x) {
    return 1.f - __fdividef(2.f, 1.f + __expf(2.f * x));
}
__device__ __forceinline__ uint32_t pack_bf16(float a, float b, float* lo_a, float* lo_b) {
    __nv_bfloat16 ha = __float2bfloat16(a);
    __nv_bfloat16 hb = __float2bfloat16(b);
    *lo_a = a - __bfloat162float(ha);
    *lo_b = b - __bfloat162float(hb);
    return (uint32_t)__bfloat16_as_ushort(ha) | ((uint32_t)__bfloat16_as_ushort(hb) << 16);
}
__device__ __forceinline__ uint32_t pack_bf16_only(float a, float b) {
    return (uint32_t)__bfloat16_as_ushort(__float2bfloat16(a)) |
           ((uint32_t)__bfloat16_as_ushort(__float2bfloat16(b)) << 16);
}

// ---------------- init: reset barriers, seed h frag slab from h0 -------------
__global__ void init_state(const float* s1_h0, const float* s2_h0) {
    int idx = blockIdx.x * blockDim.x + threadIdx.x;
    if (idx < 2) { g_cnt2[idx] = 0; g_epoch2[idx] = 0; }
    if (idx >= 2 * 128 * (Hq / 2)) return;
    int jj  = idx % (Hq / 2);       // u32 pair index
    int j   = jj * 2;
    int m   = (idx / (Hq / 2)) % 128;
    int dir = idx / ((Hq / 2) * 128);
    int seq = m >> 6, b = m & 63;
    const float* h0 = seq ? s2_h0 : s1_h0;
    float h0a = h0[(dir * Bq + b) * Hq + j];
    float h0b = h0[(dir * Bq + b) * Hq + j + 1];
    float la, lb;
    uint32_t uhi = pack_bf16(h0a, h0b, &la, &lb);
    uint32_t ulo = pack_bf16_only(la, lb);
    int mb   = m >> 4;
    int kt   = j >> 4;
    int lane = (m & 7) * 4 + ((j >> 1) & 3);
    int slot = ((j & 15) >> 3) * 2 + ((m & 15) >> 3);
    d_h16f[0][0][dir][mb][kt][lane][slot] = uhi;
    d_h16f[0][1][dir][mb][kt][lane][slot] = ulo;
}

// ---------------- split Whh into bf16 hi/lo ----------------------------------
__global__ void prep_weights(const float* __restrict__ Whh_f,
                             const float* __restrict__ Whh_b) {
    int idx = blockIdx.x * blockDim.x + threadIdx.x;
    if (idx >= 2 * G4H * Hq) return;
    int dir = idx / (G4H * Hq);
    int r   = idx % (G4H * Hq);
    float w = (dir ? Whh_b : Whh_f)[r];
    __nv_bfloat16 hi = __float2bfloat16(w);
    __nv_bfloat16 lo = __float2bfloat16(w - __bfloat162float(hi));
    int n = r / Hq, k = r % Hq;
    d_Wb16[dir][0][n][k] = hi;
    d_Wb16[dir][1][n][k] = lo;
}

// ---------------- gather tokens + convert emb rows to bf16 hi/lo -------------
__global__ void gather_convert(const int* __restrict__ s1, const int* __restrict__ s2,
                               const float* __restrict__ emb) {
    int idx = blockIdx.x * blockDim.x + threadIdx.x;
    if (idx >= NROWS * KE) return;
    int m = idx / KE, k = idx % KE;
    int tok = (m < RPS) ? s1[m] : s2[m - RPS];
    float v = (k < Eq) ? emb[(long)tok * Eq + k] : 0.f;
    __nv_bfloat16 hi = __float2bfloat16(v);
    d_x16[0][m][k] = hi;
    d_x16[1][m][k] = __float2bfloat16(v - __bfloat162float(hi));
}

// ---------------- convert Wih (both dirs) to bf16 hi/lo + combined bias ------
__global__ void convert_wih(const float* __restrict__ Wih_f, const float* __restrict__ Wih_b,
                            const float* __restrict__ b_f, const float* __restrict__ b_b) {
    int idx = blockIdx.x * blockDim.x + threadIdx.x;
    if (idx >= 2 * G4H * KE) return;
    int n = idx / KE, k = idx % KE;
    int dir = n >> 11, nn = n & 2047;
    const float* W = dir ? Wih_b : Wih_f;
    float v = (k < Eq) ? W[(long)nn * Eq + k] : 0.f;
    __nv_bfloat16 hi = __float2bfloat16(v);
    d_W16[0][n][k] = hi;
    d_W16[1][n][k] = __float2bfloat16(v - __bfloat162float(hi));
    if (k == 0) d_biasC[n] = (dir ? b_b : b_f)[nn];
}

// ---------------- convert S1W to bf16 hi/lo -----------------------------------
__global__ void convert_s1w(const float* __restrict__ S1W) {
    int idx = blockIdx.x * blockDim.x + threadIdx.x;
    if (idx >= Cq * D2H) return;
    float v = S1W[idx];
    int c = idx / D2H, k = idx % D2H;
    __nv_bfloat16 hi = __float2bfloat16(v);
    d_S1W16[0][c][k] = hi;
    d_S1W16[1][c][k] = __float2bfloat16(v - __bfloat162float(hi));
}

// ---------------- mma.sync bf16 helper ---------------------------------------
__device__ __forceinline__ void mma_bf16(float* d, const uint32_t* a, const uint32_t* b) {
    asm volatile(
        "mma.sync.aligned.m16n8k16.row.col.f32.bf16.bf16.f32 "
        "{%0,%1,%2,%3}, {%4,%5,%6,%7}, {%8,%9}, {%0,%1,%2,%3};\n"
        : "+f"(d[0]), "+f"(d[1]), "+f"(d[2]), "+f"(d[3])
        : "r"(a[0]), "r"(a[1]), "r"(a[2]), "r"(a[3]),
          "r"(b[0]), "r"(b[1]));
}

// ---------------- xW via tensor cores: [16384,304] @ [304,4096] --------------
__global__ __launch_bounds__(256)
void xw_mma() {
    const int lane = threadIdx.x & 31;
    const int warp = threadIdx.x >> 5;
    const int wm = warp & 1, wn = warp >> 1;
    const int m0 = blockIdx.y * 64 + wm * 32;
    const int n0 = blockIdx.x * 256 + wn * 64;
    const int RS = KE / 2;                 // u32 row stride (152)
    const int kc = lane & 3;
    const int rr = lane >> 2;

    const uint32_t* Xhi = (const uint32_t*)&d_x16[0][0][0];
    const uint32_t* Xlo = (const uint32_t*)&d_x16[1][0][0];
    const uint32_t* Whi = (const uint32_t*)&d_W16[0][0][0];
    const uint32_t* Wlo = (const uint32_t*)&d_W16[1][0][0];

    float acc[2][8][4] = {};

    for (int kt = 0; kt < KE / 16; ++kt) {
        const int k0 = kt * 8;
        uint32_t aH[2][4], aL[2][4];
#pragma unroll
        for (int mt = 0; mt < 2; ++mt) {
            int base = (m0 + mt * 16 + rr) * RS + k0 + kc;
            aH[mt][0] = Xhi[base];          aH[mt][1] = Xhi[base + 8 * RS];
            aH[mt][2] = Xhi[base + 4];      aH[mt][3] = Xhi[base + 8 * RS + 4];
            aL[mt][0] = Xlo[base];          aL[mt][1] = Xlo[base + 8 * RS];
            aL[mt][2] = Xlo[base + 4];      aL[mt][3] = Xlo[base + 8 * RS + 4];
        }
#pragma unroll
        for (int nt = 0; nt < 8; ++nt) {
            int bb = (n0 + nt * 8 + rr) * RS + k0 + kc;
            uint32_t bh[2] = { Whi[bb], Whi[bb + 4] };
            uint32_t bl[2] = { Wlo[bb], Wlo[bb + 4] };
#pragma unroll
            for (int mt = 0; mt < 2; ++mt) {
                mma_bf16(acc[mt][nt], aH[mt], bh);
                mma_bf16(acc[mt][nt], aL[mt], bh);
                mma_bf16(acc[mt][nt], aH[mt], bl);
            }
        }
    }
#pragma unroll
    for (int mt = 0; mt < 2; ++mt)
#pragma unroll
        for (int nt = 0; nt < 8; ++nt) {
            int r  = m0 + mt * 16 + rr;
            int cc = n0 + nt * 8 + (lane & 3) * 2;
#pragma unroll
            for (int i = 0; i < 4; ++i) {
                int m = r + (i >> 1) * 8;
                int n = cc + (i & 1);
                int dir = n >> 11, nn = n & 2047;
                d_xW[dir][m][nn] = acc[mt][nt][i] + d_biasC[n];
            }
        }
}

// ---------------- persistent LSTM: all 128 steps, tensor cores ---------------
// 128 CTAs (64/dir). h in fragment-major layout: LDG.128 loads, STG.64 stores.
// Whh in smem packed (bh0,bh1,bl0,bl1): LDS.128. 3-deep prefetch ring.
__global__ __launch_bounds__(256)
void lstm_persist(const int* __restrict__ s1_len, const int* __restrict__ s2_len,
                  const float* __restrict__ s1_c0, const float* __restrict__ s2_c0) {
    extern __shared__ uint32_t sWf[];   // 64KB: [g(4)][kt(32)][lane(32)][bh0,bh1,bl0,bl1]
    const int tid  = threadIdx.x;
    const int lane = tid & 31;
    const int warp = tid >> 5;
    const int dir  = blockIdx.x & 1;
    const int j0   = (blockIdx.x >> 1) * 8;

    // ---- packed fragment-major weight fill (once) ----
    for (int i = tid; i < 4096; i += 256) {
        int g  = i >> 10;
        int kt = (i >> 5) & 31;
        int l  = i & 31;
        int n  = l >> 2;
        int k0 = kt * 16 + (l & 3) * 2;
        const uint32_t* srcH = (const uint32_t*)&d_Wb16[dir][0][g * Hq + j0 + n][0];
        const uint32_t* srcL = (const uint32_t*)&d_Wb16[dir][1][g * Hq + j0 + n][0];
        uint4 v;
        v.x = srcH[k0 >> 1];       v.y = srcH[(k0 + 8) >> 1];
        v.z = srcL[k0 >> 1];       v.w = srcL[(k0 + 8) >> 1];
        *(uint4*)&sWf[i * 4] = v;
    }

    // ---- per-thread ownership ----
    const int m0  = warp * 16;
    const int seq = m0 >> 6;
    const int r0  = m0 + (lane >> 2);
    const int c0j = j0 + (lane & 3) * 2;
    const int*   lens = seq ? s2_len : s1_len;
    const float* c0p  = seq ? s2_c0  : s1_c0;
    const int b0 = r0 & 63;
    const int len_[2] = { lens[b0], lens[b0 + 8] };
    const int ktW   = j0 >> 4;          // this CTA's k-tile in the h slab
    const int kslot = (j0 >> 3) & 1;    // 0: slots {0,1} (a0,a1); 1: slots {2,3}

    float creg[4];
#pragma unroll
    for (int ri = 0; ri < 2; ++ri)
#pragma unroll
        for (int ci = 0; ci < 2; ++ci)
            creg[ri * 2 + ci] = c0p[(dir * Bq + b0 + 8 * ri) * Hq + c0j + ci];

    __syncthreads();

    unsigned myep = 0;

    for (int t = 0; t < Tq; ++t) {
        const int p = t & 1;
        // per-warp fragment base: [p][split][dir][mb=warp][kt][lane][4]
        const uint32_t* HhiF = &d_h16f[p][0][dir][warp][0][0][0];
        const uint32_t* HloF = &d_h16f[p][1][dir][warp][0][0][0];

        // ---- prefetch xW gate values for this step ----
        int rowx_[2];
        float2 pgi[2], pgf[2], pgg[2], pgo[2];
#pragma unroll
        for (int ri = 0; ri < 2; ++ri) {
            int b = b0 + 8 * ri;
            int len = len_[ri];
            int tpos = dir ? ((t < len) ? (len - 1 - t) : t) : t;
            rowx_[ri] = (seq * Bq + b) * Tq + tpos;
            const float* xwr = &d_xW[dir][rowx_[ri]][0];
            pgi[ri] = __ldcs((const float2*)&xwr[c0j]);
            pgf[ri] = __ldcs((const float2*)&xwr[Hq + c0j]);
            pgg[ri] = __ldcs((const float2*)&xwr[2 * Hq + c0j]);
            pgo[ri] = __ldcs((const float2*)&xwr[3 * Hq + c0j]);
        }

        float acc[4][4] = {};
        uint32_t aH[3][4], aL[3][4];

#define LOADA(buf, ktv) {                                                         \
        uint4 vh = __ldcg((const uint4*)(HhiF + (ktv) * 128 + lane * 4));         \
        aH[buf][0] = vh.x; aH[buf][1] = vh.y; aH[buf][2] = vh.z; aH[buf][3] = vh.w;\
        uint4 vl = __ldcg((const uint4*)(HloF + (ktv) * 128 + lane * 4));         \
        aL[buf][0] = vl.x; aL[buf][1] = vl.y; aL[buf][2] = vl.z; aL[buf][3] = vl.w; }

        LOADA(0, 0);
        LOADA(1, 1);

#pragma unroll
        for (int kt = 0; kt < 32; ++kt) {
            const int cur = kt % 3;
            if (kt < 30) { LOADA((kt + 2) % 3, kt + 2); }
#pragma unroll
            for (int g = 0; g < 4; ++g) {
                uint4 wv = *(const uint4*)&sWf[((g * 32 + kt) * 32 + lane) * 4];
                uint32_t bh[2] = { wv.x, wv.y };
                uint32_t bl[2] = { wv.z, wv.w };
                mma_bf16(acc[g], aH[cur], bh);
                mma_bf16(acc[g], aL[cur], bh);
                mma_bf16(acc[g], aH[cur], bl);
            }
        }
#undef LOADA

        // ---- epilogue: gates, cell/h update, publish h (packed) ----
        uint32_t hhi[2], hlo[2];   // per ri: packed (h(c0j), h(c0j+1))
#pragma unroll
        for (int ri = 0; ri < 2; ++ri) {
            const int rowx = rowx_[ri];
            float hv[2];
#pragma unroll
            for (int ci = 0; ci < 2; ++ci) {
                const int ai = ri * 2 + ci;
                float gi = acc[0][ai] + (ci ? pgi[ri].y : pgi[ri].x);
                float gf = acc[1][ai] + (ci ? pgf[ri].y : pgf[ri].x);
                float gg = acc[2][ai] + (ci ? pgg[ri].y : pgg[ri].x);
                float go = acc[3][ai] + (ci ? pgo[ri].y : pgo[ri].x);
                float c  = fsigmoid(gf) * creg[ai] + fsigmoid(gi) * ftanh(gg);
                hv[ci]   = fsigmoid(go) * ftanh(c);
                creg[ai] = c;
            }
            float la, lb;
            hhi[ri] = pack_bf16(hv[0], hv[1], &la, &lb);
            hlo[ri] = pack_bf16_only(la, lb);
            *(uint32_t*)&d_Ho16[0][rowx][dir * Hq + c0j] = hhi[ri];
            *(uint32_t*)&d_Ho16[1][rowx][dir * Hq + c0j] = hlo[ri];
        }
        // h state: one STG.64 per split (slots kslot*2, kslot*2+1 are ri=0, ri=1)
        *(uint2*)&d_h16f[p ^ 1][0][dir][warp][ktW][lane][kslot * 2] = make_uint2(hhi[0], hhi[1]);
        *(uint2*)&d_h16f[p ^ 1][1][dir][warp][ktW][lane][kslot * 2] = make_uint2(hlo[0], hlo[1]);

        // ---- per-direction grid barrier ----
        __syncthreads();
        if (tid == 0) {
            __threadfence();
            unsigned arrived = atomicAdd(&g_cnt2[dir], 1);
            if (arrived == NCTA / 2 - 1) {
                g_cnt2[dir] = 0;
                __threadfence();
                atomicExch(&g_epoch2[dir], myep + 1);
            } else {
                while (*(volatile unsigned*)&g_epoch2[dir] <= myep) { }
            }
            __threadfence();
        }
        myep++;
        __syncthreads();
    }
}

// ---------------- attention projection via tensor cores ----------------------
__global__ __launch_bounds__(256)
void attn_mma() {
    const int lane = threadIdx.x & 31;
    const int warp = threadIdx.x >> 5;
    const int wm = warp & 1, wn = warp >> 1;
    const int m0 = blockIdx.y * 64 + wm * 32;
    const int n0 = wn * 64;
    const int RS = D2H / 2;
    const int kc = lane & 3;
    const int rr = lane >> 2;

    const uint32_t* Xhi = (const uint32_t*)&d_Ho16[0][0][0];
    const uint32_t* Xlo = (const uint32_t*)&d_Ho16[1][0][0];
    const uint32_t* Whi = (const uint32_t*)&d_S1W16[0][0][0];
    const uint32_t* Wlo = (const uint32_t*)&d_S1W16[1][0][0];

    float acc[2][8][4] = {};

    for (int kt = 0; kt < D2H / 16; ++kt) {
        const int k0 = kt * 8;
        uint32_t aH[2][4], aL[2][4];
#pragma unroll
        for (int mt = 0; mt < 2; ++mt) {
            int base = (m0 + mt * 16 + rr) * RS + k0 + kc;
            aH[mt][0] = Xhi[base];          aH[mt][1] = Xhi[base + 8 * RS];
            aH[mt][2] = Xhi[base + 4];      aH[mt][3] = Xhi[base + 8 * RS + 4];
            aL[mt][0] = Xlo[base];          aL[mt][1] = Xlo[base + 8 * RS];
            aL[mt][2] = Xlo[base + 4];      aL[mt][3] = Xlo[base + 8 * RS + 4];
        }
#pragma unroll
        for (int nt = 0; nt < 8; ++nt) {
            int bb = (n0 + nt * 8 + rr) * RS + k0 + kc;
            uint32_t bh[2] = { Whi[bb], Whi[bb + 4] };
            uint32_t bl[2] = { Wlo[bb], Wlo[bb + 4] };
#pragma unroll
            for (int mt = 0; mt < 2; ++mt) {
                mma_bf16(acc[mt][nt], aH[mt], bh);
                mma_bf16(acc[mt][nt], aL[mt], bh);
                mma_bf16(acc[mt][nt], aH[mt], bl);
            }
        }
    }
#pragma unroll
    for (int mt = 0; mt < 2; ++mt)
#pragma unroll
        for (int nt = 0; nt < 8; ++nt) {
            int r  = m0 + mt * 16 + rr;
            int cc = n0 + nt * 8 + (lane & 3) * 2;
#pragma unroll
            for (int i = 0; i < 4; ++i)
                d_P[r + (i >> 1) * 8][cc + (i & 1)] = acc[mt][nt][i];
        }
}

// ---------------- masked softmax attention pooling ---------------------------
__global__ __launch_bounds__(128)
void attn_pool(const int* __restrict__ s1_len, const int* __restrict__ s2_len,
               const float* __restrict__ S2W) {
    __shared__ float sS2[Cq];
    __shared__ float ssc[Tq];
    __shared__ float red[Tq];
    int sb = blockIdx.x;
    int seq = sb >> 6, b = sb & 63;
    int t = threadIdx.x;
    for (int c = t; c < Cq; c += Tq) sS2[c] = S2W[c];
    __syncthreads();

    long row = (long)sb * Tq + t;
    float s = 0.f;
    for (int c = 0; c < Cq; ++c) s += ftanh(d_P[row][c]) * sS2[c];
    int len = (seq ? s2_len : s1_len)[b];
    ssc[t] = (t < len) ? s : -1e9f;
    __syncthreads();

    red[t] = ssc[t]; __syncthreads();
    for (int o = 64; o > 0; o >>= 1) { if (t < o) red[t] = fmaxf(red[t], red[t + o]); __syncthreads(); }
    float mx = red[0]; __syncthreads();
    float ex = expf(ssc[t] - mx);
    red[t] = ex; __syncthreads();
    for (int o = 64; o > 0; o >>= 1) { if (t < o) red[t] += red[t + o]; __syncthreads(); }
    float inv = 1.f / red[0];
    __syncthreads();
    ssc[t] = ex * inv;
    __syncthreads();

    long rowbase = (long)sb * Tq;
    for (int d = t; d < D2H; d += Tq) {
        float acc = 0.f;
        for (int tt = 0; tt < Tq; ++tt) {
            long rw = rowbase + tt;
            float h = __bfloat162float(d_Ho16[0][rw][d]) + __bfloat162float(d_Ho16[1][rw][d]);
            acc += ssc[tt] * h;
        }
        d_r[seq][b][d] = acc;
    }
}

// ---------------- final MLP head + sigmoid ----------------------------------
__global__ __launch_bounds__(512)
void final_mlp(const float* __restrict__ mlpW, const float* __restrict__ mlpb,
               const float* __restrict__ outW, const float* __restrict__ outb,
               float* __restrict__ out) {
    __shared__ float merged[4 * Hq];
    __shared__ float smlp[Mq];
    __shared__ float red[16];
    int b = blockIdx.x;
    int tid = threadIdx.x;

    for (int d = tid; d < 2 * D2H; d += Mq) {
        float v;
        if (d < D2H) v = d_r[0][b][d] + d_r[1][b][d];
        else { float df = d_r[0][b][d - D2H] - d_r[1][b][d - D2H]; v = df * df; }
        merged[d] = v;
    }
    __syncthreads();

    int warp = tid >> 5, lane = tid & 31;
    for (int m = warp * 32; m < warp * 32 + 32; ++m) {
        float p = 0.f;
        for (int d = lane; d < 4 * Hq; d += 32) p += merged[d] * mlpW[(long)m * 4 * Hq + d];
        for (int o = 16; o > 0; o >>= 1) p += __shfl_down_sync(0xffffffff, p, o);
        if (lane == 0) smlp[m] = p + mlpb[m];
    }
    __syncthreads();

    float p = smlp[tid] * outW[tid];
    for (int o = 16; o > 0; o >>= 1) p += __shfl_down_sync(0xffffffff, p, o);
    if (lane == 0) red[warp] = p;
    __syncthreads();
    if (tid == 0) {
        float l = outb[0];
        for (int w = 0; w < 16; ++w) l += red[w];
        out[b] = 1.f / (1.f + expf(-l));
    }
}

// ---------------- launch ------------------------------------------------------
extern "C" void kernel_launch(void* const* d_in, const int* in_sizes, int n_in,
                              void* d_out, int out_size) {
    const int*   s1     = (const int*)d_in[0];
    const int*   s2     = (const int*)d_in[1];
    const int*   s1_len = (const int*)d_in[2];
    const int*   s2_len = (const int*)d_in[3];
    const float* s1_h0  = (const float*)d_in[4];
    const float* s1_c0  = (const float*)d_in[5];
    const float* s2_h0  = (const float*)d_in[6];
    const float* s2_c0  = (const float*)d_in[7];
    const float* emb    = (const float*)d_in[8];
    const float* Wih_f  = (const float*)d_in[9];
    const float* Whh_f  = (const float*)d_in[10];
    const float* b_f    = (const float*)d_in[11];
    const float* Wih_b  = (const float*)d_in[12];
    const float* Whh_b  = (const float*)d_in[13];
    const float* b_b    = (const float*)d_in[14];
    const float* S1W    = (const float*)d_in[15];
    const float* S2W    = (const float*)d_in[16];
    const float* mlpW   = (const float*)d_in[17];
    const float* mlpb   = (const float*)d_in[18];
    const float* outW   = (const float*)d_in[19];
    const float* outb   = (const float*)d_in[20];
    float* out = (float*)d_out;

    const int smem_lstm = 16384 * (int)sizeof(uint32_t);   // 64KB
    cudaFuncSetAttribute(lstm_persist, cudaFuncAttributeMaxDynamicSharedMemorySize, smem_lstm);

    init_state<<<(2 * 128 * (Hq / 2) + 255) / 256, 256>>>(s1_h0, s2_h0);
    prep_weights<<<(2 * G4H * Hq + 255) / 256, 256>>>(Whh_f, Whh_b);
    gather_convert<<<(NROWS * KE + 255) / 256, 256>>>(s1, s2, emb);
    convert_wih<<<(2 * G4H * KE + 255) / 256, 256>>>(Wih_f, Wih_b, b_f, b_b);
    convert_s1w<<<(Cq * D2H + 255) / 256, 256>>>(S1W);

    xw_mma<<<dim3(16, 256), 256>>>();                  // both dirs fused

    lstm_persist<<<NCTA, 256, smem_lstm>>>(s1_len, s2_len, s1_c0, s2_c0);

    attn_mma<<<dim3(1, 256), 256>>>();
    attn_pool<<<128, 128>>>(s1_len, s2_len, S2W);
    final_mlp<<<Bq, 512>>>(mlpW, mlpb, outW, outb, out);
}